// round 8
// baseline (speedup 1.0000x reference)
#include <cuda_runtime.h>
#include <cstddef>

typedef unsigned long long ull;

// ===================== problem constants =====================
// B=8, C=256, H=W=64, HD=64, NH=4 heads, BH=B*NH=32, N=1024 coarse tokens,
// KF=256 selected patches, PS=2.

// ===================== device scratch (no allocations allowed) =============
__device__ float g_xd[2097152];      // [8,256,32,32] downsampled
__device__ float g_tok[2097152];     // [32,1024,64] tokens (coarse, then fine)
__device__ float g_q[2097152];       // [32,1024,64] (q pre-scaled by 0.125)
__device__ float g_kk[2097152];      // [32,1024,64]
__device__ float g_v[2097152];       // [32,1024,64]
__device__ float g_attn[33554432];   // [32,1024,1024]
__device__ float g_part[262144];     // [32,8,1024] colsum partials
__device__ float g_score[32768];     // [32,1024]
__device__ int   g_topk[8192];       // [32,256]
__device__ float g_aout[2097152];    // [8,256,32,32] coarse attn out (image layout)
__device__ float g_coarse[8388608];  // [8,256,64,64]
__device__ float g_outf[2097152];    // [32,1024,64] fine attn out
__device__ float g_y1[8388608];      // [8,256,64,64] after dw+bn1+relu6
__device__ float g_upw[1048576];     // [4 parity][256 co][256 ci *4 taps]

// ===================== f32x2 packed-FMA primitives ==========================
__device__ __forceinline__ ull dup2(float b) {
  ull r;
  asm("mov.b64 %0, {%1, %1};" : "=l"(r) : "f"(b));
  return r;
}
__device__ __forceinline__ void fma2(ull& acc, ull a, ull b) {
  asm("fma.rn.f32x2 %0, %1, %2, %0;" : "+l"(acc) : "l"(a), "l"(b));
}
__device__ __forceinline__ void unpack_acc(const ull (&acc)[4][8], float (&f)[8][8]) {
#pragma unroll
  for (int p = 0; p < 4; p++)
#pragma unroll
    for (int j = 0; j < 8; j++)
      asm("mov.b64 {%0, %1}, %2;"
          : "=f"(f[2 * p][j]), "=f"(f[2 * p + 1][j]) : "l"(acc[p][j]));
}

// ===================== shared loaders =======================================
// As[k][m] transposed-A staging (BM=128, BK=16), 256 threads.
__device__ __forceinline__ void ldA_rowmajor(float (&As)[16][132],
    const float* __restrict__ A, int lda, int m0, int k0, int tid) {
  int m  = tid >> 1;             // 0..127
  int kq = (tid & 1) * 8;        // 0 or 8
  const float* src = A + (size_t)(m0 + m) * lda + k0 + kq;
  float4 x0 = *(const float4*)(src);
  float4 x1 = *(const float4*)(src + 4);
  As[kq + 0][m] = x0.x; As[kq + 1][m] = x0.y;
  As[kq + 2][m] = x0.z; As[kq + 3][m] = x0.w;
  As[kq + 4][m] = x1.x; As[kq + 5][m] = x1.y;
  As[kq + 6][m] = x1.z; As[kq + 7][m] = x1.w;
}

// Bs[k][n], BN=128, 256 threads, row-major source.
__device__ __forceinline__ void ldB_rm128(float (&Bs)[16][132],
    const float* __restrict__ Bm, int ldb, int k0, int n0, int tid) {
  int kk = tid >> 4;             // 0..15
  int nn = (tid & 15) * 8;       // 0..120
  const float* src = Bm + (size_t)(k0 + kk) * ldb + n0 + nn;
  *(float4*)&Bs[kk][nn]     = *(const float4*)(src);
  *(float4*)&Bs[kk][nn + 4] = *(const float4*)(src + 4);
}

// Bs[k][n] = Bm[n0+n][k0+k], BN=128, BK=16, 256 threads (for QK^T).
__device__ __forceinline__ void ldB_t128(float (&Bs)[16][132],
    const float* __restrict__ Bm, int ldb, int k0, int n0, int tid) {
  int n  = tid >> 1;             // 0..127
  int kq = (tid & 1) * 8;       // 0 or 8
  const float* src = Bm + (size_t)(n0 + n) * ldb + k0 + kq;
  float4 x0 = *(const float4*)(src);
  float4 x1 = *(const float4*)(src + 4);
  Bs[kq + 0][n] = x0.x; Bs[kq + 1][n] = x0.y;
  Bs[kq + 2][n] = x0.z; Bs[kq + 3][n] = x0.w;
  Bs[kq + 4][n] = x1.x; Bs[kq + 5][n] = x1.y;
  Bs[kq + 6][n] = x1.z; Bs[kq + 7][n] = x1.w;
}

// 8x8 packed-FMA micro-tile: pairs along M come free from As LDS.128.
__device__ __forceinline__ void fma_tile88(const float (&As)[16][132],
    const float (&Bs)[16][132], ull (&acc)[4][8], int tx, int ty) {
#pragma unroll
  for (int kk = 0; kk < 16; kk++) {
    ulonglong2 a0 = *(const ulonglong2*)&As[kk][ty * 8];
    ulonglong2 a1 = *(const ulonglong2*)&As[kk][ty * 8 + 4];
    float4 b0 = *(const float4*)&Bs[kk][tx * 8];
    float4 b1 = *(const float4*)&Bs[kk][tx * 8 + 4];
    ull ap[4] = {a0.x, a0.y, a1.x, a1.y};
    ull bp[8] = {dup2(b0.x), dup2(b0.y), dup2(b0.z), dup2(b0.w),
                 dup2(b1.x), dup2(b1.y), dup2(b1.z), dup2(b1.w)};
#pragma unroll
    for (int p = 0; p < 4; p++)
#pragma unroll
      for (int j = 0; j < 8; j++) fma2(acc[p][j], ap[p], bp[j]);
  }
}

// ---- legacy 8x4 microkernel pieces (kept for k_qkv, N=192) ----
__device__ __forceinline__ void ldB_rowmajor(float (&Bs)[16][68],
    const float* __restrict__ Bm, int ldb, int k0, int n0, int tid) {
  int kk = tid >> 4;
  int nn = (tid & 15) * 4;
  float4 x = *(const float4*)(Bm + (size_t)(k0 + kk) * ldb + n0 + nn);
  *(float4*)&Bs[kk][nn] = x;
}
__device__ __forceinline__ void fma_tile(const float (&As)[16][132],
    const float (&Bs)[16][68], float (&acc)[8][4], int tx, int ty) {
#pragma unroll
  for (int kk = 0; kk < 16; kk++) {
    float4 a0 = *(const float4*)&As[kk][ty * 8];
    float4 a1 = *(const float4*)&As[kk][ty * 8 + 4];
    float4 b4 = *(const float4*)&Bs[kk][tx * 4];
    float av[8] = {a0.x, a0.y, a0.z, a0.w, a1.x, a1.y, a1.z, a1.w};
    float bv[4] = {b4.x, b4.y, b4.z, b4.w};
#pragma unroll
    for (int i = 0; i < 8; i++)
#pragma unroll
      for (int j = 0; j < 4; j++) acc[i][j] += av[i] * bv[j];
  }
}

// ===================== 0) repack ConvTranspose weights ======================
__global__ void k_repack_upw(const float* __restrict__ upw, float* __restrict__ dst) {
  int idx = blockIdx.x * 256 + threadIdx.x;   // 1048576
  int t  = idx & 3;
  int ci = (idx >> 2) & 255;
  int co = (idx >> 10) & 255;
  int pc = idx >> 18;
  int py = pc >> 1, px = pc & 1;
  int ky = ((py + 1) & 1) + ((t >> 1) << 1);
  int kx = ((px + 1) & 1) + ((t & 1) << 1);
  dst[idx] = upw[((ci * 256 + co) * 4 + ky) * 4 + kx];
}

// ===================== 1) conv 4x4 stride2 pad1 (implicit GEMM, f32x2) ======
// M=256 co, N=8192 (b, 32x32), K=4096 (ci*16 + ky*4 + kx). BN=128.
__global__ void __launch_bounds__(256, 2) k_conv_down(const float* __restrict__ x,
    const float* __restrict__ w, const float* __restrict__ bias,
    float* __restrict__ out) {
  __shared__ float As[16][132];
  __shared__ float Bs[16][132];
  ull acc[4][8] = {};
  int tid = threadIdx.x, tx = tid & 15, ty = tid >> 4;
  int m0 = blockIdx.y * 128, n0 = blockIdx.x * 128;
  int lkk = tid >> 4, lnn = (tid & 15) * 8;
  int bimg = n0 >> 10, rem0 = (n0 & 1023) + lnn;
  const float* xb = x + ((size_t)bimg << 20);
  for (int k0 = 0; k0 < 4096; k0 += 16) {
    ldA_rowmajor(As, w, 4096, m0, k0, tid);
    {
      int k = k0 + lkk;
      int ci = k >> 4, ky = (k >> 2) & 3, kx = k & 3;
      const float* xc = xb + ((size_t)ci << 12);
#pragma unroll
      for (int j = 0; j < 8; j++) {
        int rem = rem0 + j;
        int oy = rem >> 5, ox = rem & 31;
        int iy = 2 * oy + ky - 1, ix = 2 * ox + kx - 1;
        float vv = 0.f;
        if ((unsigned)iy < 64u && (unsigned)ix < 64u) vv = xc[(iy << 6) + ix];
        Bs[lkk][lnn + j] = vv;
      }
    }
    __syncthreads();
    fma_tile88(As, Bs, acc, tx, ty);
    __syncthreads();
  }
  float accf[8][8];
  unpack_acc(acc, accf);
  int rem = (n0 & 1023) + tx * 8;
#pragma unroll
  for (int i = 0; i < 8; i++) {
    int m = m0 + ty * 8 + i;
    float bi = bias[m];
    float* dst = &out[(((bimg << 8) + m) << 10) + rem];
    *(float4*)dst = make_float4(accf[i][0] + bi, accf[i][1] + bi,
                                accf[i][2] + bi, accf[i][3] + bi);
    *(float4*)(dst + 4) = make_float4(accf[i][4] + bi, accf[i][5] + bi,
                                      accf[i][6] + bi, accf[i][7] + bi);
  }
}

// ===================== 2) image -> token transpose (coarse) =================
__global__ void k_tokc(const float* __restrict__ xd, float* __restrict__ tok) {
  __shared__ float s[64][65];
  int bh = blockIdx.x, nch = blockIdx.y;   // 32 x 16
  int b = bh >> 2, h = bh & 3;
  int tid = threadIdx.x;
  int n0 = nch * 64;
#pragma unroll
  for (int i = 0; i < 16; i++) {
    int lin = i * 256 + tid;
    int d = lin >> 6, nn = lin & 63;
    s[d][nn] = xd[(((b << 8) + (h << 6) + d) << 10) + n0 + nn];
  }
  __syncthreads();
#pragma unroll
  for (int i = 0; i < 16; i++) {
    int lin = i * 256 + tid;
    int nn = lin >> 6, d = lin & 63;
    tok[((size_t)bh << 16) + ((size_t)(n0 + nn) << 6) + d] = s[d][nn];
  }
}

// ===================== 3) QKV GEMM (legacy 8x4 path, N=192) =================
__global__ void __launch_bounds__(256) k_qkv(const float* __restrict__ tok,
    const float* __restrict__ wqkv, const float* __restrict__ bqkv,
    float* __restrict__ q, float* __restrict__ kmat, float* __restrict__ v) {
  __shared__ float As[16][132];
  __shared__ float Bs[16][68];
  float acc[8][4] = {};
  int tid = threadIdx.x, tx = tid & 15, ty = tid >> 4;
  int bh = blockIdx.z;
  int m0 = blockIdx.y * 128, n0 = blockIdx.x * 64;
  const float* A = tok + ((size_t)bh << 16);
  for (int k0 = 0; k0 < 64; k0 += 16) {
    ldA_rowmajor(As, A, 64, m0, k0, tid);
    ldB_rowmajor(Bs, wqkv, 192, k0, n0, tid);
    __syncthreads();
    fma_tile(As, Bs, acc, tx, ty);
    __syncthreads();
  }
  int sec = n0 >> 6;                               // 0:q 1:k 2:v
  float* dst = (sec == 0) ? q : ((sec == 1) ? kmat : v);
  float mul = (sec == 0) ? 0.125f : 1.0f;          // HD^-0.5 folded into q
  int d0 = tx * 4;
#pragma unroll
  for (int i = 0; i < 8; i++) {
    int m = m0 + ty * 8 + i;
    float4 o;
    o.x = (acc[i][0] + bqkv[n0 + d0 + 0]) * mul;
    o.y = (acc[i][1] + bqkv[n0 + d0 + 1]) * mul;
    o.z = (acc[i][2] + bqkv[n0 + d0 + 2]) * mul;
    o.w = (acc[i][3] + bqkv[n0 + d0 + 3]) * mul;
    *(float4*)&dst[((size_t)bh << 16) + ((size_t)m << 6) + d0] = o;
  }
}

// ===================== 4) S = q @ k^T  (f32x2, BN=128) ======================
__global__ void __launch_bounds__(256, 2) k_qkT(const float* __restrict__ q,
    const float* __restrict__ kmat, float* __restrict__ attn) {
  __shared__ float As[16][132];
  __shared__ float Bs[16][132];
  ull acc[4][8] = {};
  int tid = threadIdx.x, tx = tid & 15, ty = tid >> 4;
  int bh = blockIdx.z, m0 = blockIdx.y * 128, n0 = blockIdx.x * 128;
  const float* A  = q    + ((size_t)bh << 16);
  const float* Bm = kmat + ((size_t)bh << 16);
  for (int k0 = 0; k0 < 64; k0 += 16) {
    ldA_rowmajor(As, A, 64, m0, k0, tid);
    ldB_t128(Bs, Bm, 64, k0, n0, tid);
    __syncthreads();
    fma_tile88(As, Bs, acc, tx, ty);
    __syncthreads();
  }
  float accf[8][8];
  unpack_acc(acc, accf);
  float* out = attn + ((size_t)bh << 20);
#pragma unroll
  for (int i = 0; i < 8; i++) {
    int m = m0 + ty * 8 + i;
    float* dst = &out[((size_t)m << 10) + n0 + tx * 8];
    *(float4*)dst = make_float4(accf[i][0], accf[i][1], accf[i][2], accf[i][3]);
    *(float4*)(dst + 4) = make_float4(accf[i][4], accf[i][5], accf[i][6], accf[i][7]);
  }
}

// ===================== 5) row softmax in place ==============================
__global__ void __launch_bounds__(256) k_softmax(float* __restrict__ attn) {
  int row = blockIdx.x, bh = blockIdx.y;
  float* p = attn + ((size_t)bh << 20) + ((size_t)row << 10);
  int tid = threadIdx.x;
  float4 v = *(float4*)&p[tid * 4];
  __shared__ float red[256];
  float mx = fmaxf(fmaxf(v.x, v.y), fmaxf(v.z, v.w));
  red[tid] = mx;
  __syncthreads();
  for (int s = 128; s > 0; s >>= 1) {
    if (tid < s) red[tid] = fmaxf(red[tid], red[tid + s]);
    __syncthreads();
  }
  mx = red[0];
  __syncthreads();
  v.x = __expf(v.x - mx); v.y = __expf(v.y - mx);
  v.z = __expf(v.z - mx); v.w = __expf(v.w - mx);
  red[tid] = (v.x + v.y) + (v.z + v.w);
  __syncthreads();
  for (int s = 128; s > 0; s >>= 1) {
    if (tid < s) red[tid] += red[tid + s];
    __syncthreads();
  }
  float inv = 1.0f / red[0];
  v.x *= inv; v.y *= inv; v.z *= inv; v.w *= inv;
  *(float4*)&p[tid * 4] = v;
}

// ===================== 6) column sums (deterministic 2-phase) ===============
__global__ void k_colsum_part(const float* __restrict__ attn, float* __restrict__ part) {
  int bh = blockIdx.x, ny = blockIdx.y, m = threadIdx.x;  // 32 x 8, 1024 thr
  const float* p = attn + ((size_t)bh << 20) + ((size_t)(ny * 128) << 10) + m;
  float a0 = 0, a1 = 0, a2 = 0, a3 = 0;
  for (int n = 0; n < 128; n += 4) {
    a0 += p[(size_t)(n + 0) << 10];
    a1 += p[(size_t)(n + 1) << 10];
    a2 += p[(size_t)(n + 2) << 10];
    a3 += p[(size_t)(n + 3) << 10];
  }
  part[(bh * 8 + ny) * 1024 + m] = (a0 + a1) + (a2 + a3);
}
__global__ void k_colsum_red(const float* __restrict__ part, float* __restrict__ score) {
  int bh = blockIdx.x, m = threadIdx.x;
  float a = 0;
#pragma unroll
  for (int i = 0; i < 8; i++) a += part[(bh * 8 + i) * 1024 + m];
  score[bh * 1024 + m] = a;
}

// ===================== 7) top-256 by rank (matches lax.top_k order) =========
__global__ void k_topk(const float* __restrict__ score, int* __restrict__ topk) {
  int bh = blockIdx.x;
  __shared__ float s[1024];
  int tid = threadIdx.x;   // 1024
  s[tid] = score[bh * 1024 + tid];
  __syncthreads();
  float mine = s[tid];
  int rank = 0;
  for (int j = 0; j < 1024; j++) {
    float o = s[j];
    rank += (o > mine) || (o == mine && j < tid);
  }
  if (rank < 256) topk[bh * 256 + rank] = tid;
}

// ===================== 8) out = attn @ v  (f32x2, 128 threads, BN=64) =======
// mode 0: write [bh][m][64] row-major (fine). mode 1: image layout aout.
__global__ void __launch_bounds__(128, 2) k_av(const float* __restrict__ attn,
    const float* __restrict__ v, float* __restrict__ out, int mode) {
  __shared__ float As[16][132];
  __shared__ float Bs[16][132];
  ull acc[4][8] = {};
  int tid = threadIdx.x, tx = tid & 7, ty = tid >> 3;   // tx 0..7, ty 0..15
  int bh = blockIdx.z, m0 = blockIdx.y * 128;
  const float* A  = attn + ((size_t)bh << 20);
  const float* Bm = v    + ((size_t)bh << 16);
  int bkk = tid >> 3, bnn = (tid & 7) * 8;
  for (int k0 = 0; k0 < 1024; k0 += 16) {
    {  // A fill: thread = one m row, 16 k values
      const float* src = A + ((size_t)(m0 + tid) << 10) + k0;
      float4 x0 = *(const float4*)(src);
      float4 x1 = *(const float4*)(src + 4);
      float4 x2 = *(const float4*)(src + 8);
      float4 x3 = *(const float4*)(src + 12);
      As[0][tid] = x0.x;  As[1][tid] = x0.y;  As[2][tid] = x0.z;  As[3][tid] = x0.w;
      As[4][tid] = x1.x;  As[5][tid] = x1.y;  As[6][tid] = x1.z;  As[7][tid] = x1.w;
      As[8][tid] = x2.x;  As[9][tid] = x2.y;  As[10][tid] = x2.z; As[11][tid] = x2.w;
      As[12][tid] = x3.x; As[13][tid] = x3.y; As[14][tid] = x3.z; As[15][tid] = x3.w;
    }
    {  // B fill: 16x64
      const float* src = Bm + (size_t)(k0 + bkk) * 64 + bnn;
      *(float4*)&Bs[bkk][bnn]     = *(const float4*)(src);
      *(float4*)&Bs[bkk][bnn + 4] = *(const float4*)(src + 4);
    }
    __syncthreads();
    fma_tile88(As, Bs, acc, tx, ty);
    __syncthreads();
  }
  float accf[8][8];
  unpack_acc(acc, accf);
  if (mode == 0) {
    float* dst0 = out + ((size_t)bh << 16);
#pragma unroll
    for (int i = 0; i < 8; i++) {
      int m = m0 + ty * 8 + i;
      float* dst = &dst0[((size_t)m << 6) + tx * 8];
      *(float4*)dst = make_float4(accf[i][0], accf[i][1], accf[i][2], accf[i][3]);
      *(float4*)(dst + 4) = make_float4(accf[i][4], accf[i][5], accf[i][6], accf[i][7]);
    }
  } else {
    int b = bh >> 2, h = bh & 3;
#pragma unroll
    for (int i = 0; i < 8; i++) {
      int m = m0 + ty * 8 + i;
#pragma unroll
      for (int j = 0; j < 8; j++) {
        int d = tx * 8 + j;
        out[(((b << 8) + (h << 6) + d) << 10) + m] = accf[i][j];
      }
    }
  }
}

// ===================== 9) ConvTranspose 4x4 s2 p1 (f32x2, per-parity) =======
// M=256 co, N=8192 (b, 32x32 half-res), K=1024 (ci*4 + tap). BN=128.
__global__ void __launch_bounds__(256, 2) k_conv_up(const float* __restrict__ ain,
    const float* __restrict__ wre, const float* __restrict__ bias,
    float* __restrict__ out) {
  __shared__ float As[16][132];
  __shared__ float Bs[16][132];
  ull acc[4][8] = {};
  int tid = threadIdx.x, tx = tid & 15, ty = tid >> 4;
  int m0 = blockIdx.y * 128, n0 = blockIdx.x * 128;
  int pc = blockIdx.z;
  int py = pc >> 1, px = pc & 1;
  const float* A = wre + (size_t)pc * 262144;
  int lkk = tid >> 4, lnn = (tid & 15) * 8;
  int dy0 = (py + 1) >> 1, dx0 = (px + 1) >> 1;
  int bimg = n0 >> 10, rem0 = (n0 & 1023) + lnn;
  const float* ab = ain + ((size_t)bimg << 18);
  for (int k0 = 0; k0 < 1024; k0 += 16) {
    ldA_rowmajor(As, A, 1024, m0, k0, tid);
    {
      int k = k0 + lkk;
      int ci = k >> 2, t = k & 3;
      int dy = dy0 - (t >> 1), dx = dx0 - (t & 1);
      const float* ac = ab + ((size_t)ci << 10);
#pragma unroll
      for (int j = 0; j < 8; j++) {
        int rem = rem0 + j;
        int iy = (rem >> 5) + dy, ix = (rem & 31) + dx;
        float vv = 0.f;
        if ((unsigned)iy < 32u && (unsigned)ix < 32u) vv = ac[(iy << 5) + ix];
        Bs[lkk][lnn + j] = vv;
      }
    }
    __syncthreads();
    fma_tile88(As, Bs, acc, tx, ty);
    __syncthreads();
  }
  float accf[8][8];
  unpack_acc(acc, accf);
  int rem = (n0 & 1023) + tx * 8;
  int oy2 = rem >> 5, ox2 = rem & 31;
  int oy = 2 * oy2 + py;
#pragma unroll
  for (int i = 0; i < 8; i++) {
    int m = m0 + ty * 8 + i;
    float bi = bias[m];
    float* dst = &out[(((bimg << 8) + m) << 12) + (oy << 6)];
#pragma unroll
    for (int j = 0; j < 8; j++) dst[2 * (ox2 + j) + px] = accf[i][j] + bi;
  }
}

// ===================== 10) gather fine tokens ===============================
__global__ void k_gather(const float* __restrict__ coarse, const int* __restrict__ topk,
                         float* __restrict__ tok) {
  int bh = blockIdx.x, chunk = blockIdx.y;   // 32 x 16
  int tid = threadIdx.x;
  int d = tid & 63;
  int b = bh >> 2, h = bh & 3;
#pragma unroll
  for (int i = 0; i < 16; i++) {
    int j = chunk * 64 + (tid >> 6) + i * 4;  // token 0..1023
    int p = j >> 2, l = j & 3;
    int qq = topk[bh * 256 + p];
    int py = ((qq >> 5) << 1) + (l >> 1);
    int px = ((qq & 31) << 1) + (l & 1);
    tok[((size_t)bh << 16) + ((size_t)j << 6) + d] =
        coarse[(((b << 8) + (h << 6) + d) << 12) + (py << 6) + px];
  }
}

// ===================== 11) scatter-add fine outputs into coarse =============
__global__ void k_scatter(const float* __restrict__ outf, const int* __restrict__ topk,
                          float* __restrict__ coarse) {
  int bh = blockIdx.x, chunk = blockIdx.y;
  int tid = threadIdx.x;
  int d = tid & 63;
  int b = bh >> 2, h = bh & 3;
#pragma unroll
  for (int i = 0; i < 16; i++) {
    int j = chunk * 64 + (tid >> 6) + i * 4;
    int p = j >> 2, l = j & 3;
    int qq = topk[bh * 256 + p];
    int py = ((qq >> 5) << 1) + (l >> 1);
    int px = ((qq & 31) << 1) + (l & 1);
    coarse[(((b << 8) + (h << 6) + d) << 12) + (py << 6) + px] +=
        outf[((size_t)bh << 16) + ((size_t)j << 6) + d];
  }
}

// ===================== 12) depthwise 3x3 + BN1 + ReLU6 ======================
__global__ void k_dw(const float* __restrict__ y, const float* __restrict__ w,
    const float* __restrict__ g, const float* __restrict__ bb,
    const float* __restrict__ mm, const float* __restrict__ vv,
    float* __restrict__ out) {
  int idx = blockIdx.x * 256 + threadIdx.x;   // 8*256*4096
  int x = idx & 63, yy = (idx >> 6) & 63, c = (idx >> 12) & 255, b = idx >> 20;
  const float* base = y + ((size_t)((b << 8) + c) << 12);
  float acc = 0.f;
#pragma unroll
  for (int ky = 0; ky < 3; ky++) {
    int iy = yy + ky - 1;
    if ((unsigned)iy >= 64u) continue;
#pragma unroll
    for (int kx = 0; kx < 3; kx++) {
      int ix = x + kx - 1;
      if ((unsigned)ix >= 64u) continue;
      acc += w[c * 9 + ky * 3 + kx] * base[(iy << 6) + ix];
    }
  }
  float inv = g[c] * rsqrtf(vv[c] + 1e-5f);
  float val = acc * inv + (bb[c] - mm[c] * inv);
  out[idx] = fminf(fmaxf(val, 0.f), 6.f);
}

// ===================== 13) pointwise 1x1 + BN2 + ReLU6 (f32x2) -> d_out =====
__global__ void __launch_bounds__(256, 2) k_pw(const float* __restrict__ y1,
    const float* __restrict__ w, const float* __restrict__ bn_g,
    const float* __restrict__ bn_b, const float* __restrict__ bn_m,
    const float* __restrict__ bn_v, float* __restrict__ out) {
  __shared__ float As[16][132];
  __shared__ float Bs[16][132];
  ull acc[4][8] = {};
  int tid = threadIdx.x, tx = tid & 15, ty = tid >> 4;
  int m0 = blockIdx.y * 128, n0 = blockIdx.x * 128;
  int lkk = tid >> 4, lnn = (tid & 15) * 8;
  int bB = n0 >> 12, remB = (n0 & 4095) + lnn;
  const float* yb = y1 + ((size_t)bB << 20);
  for (int k0 = 0; k0 < 256; k0 += 16) {
    ldA_rowmajor(As, w, 256, m0, k0, tid);
    {
      const float* src = yb + ((size_t)(k0 + lkk) << 12) + remB;
      *(float4*)&Bs[lkk][lnn]     = *(const float4*)(src);
      *(float4*)&Bs[lkk][lnn + 4] = *(const float4*)(src + 4);
    }
    __syncthreads();
    fma_tile88(As, Bs, acc, tx, ty);
    __syncthreads();
  }
  float accf[8][8];
  unpack_acc(acc, accf);
  int rem = (n0 & 4095) + tx * 8;
#pragma unroll
  for (int i = 0; i < 8; i++) {
    int m = m0 + ty * 8 + i;
    float inv = bn_g[m] * rsqrtf(bn_v[m] + 1e-5f);
    float add = bn_b[m] - bn_m[m] * inv;
    float* dst = &out[(((size_t)(bB << 8) + m) << 12) + rem];
    float4 o0, o1;
    o0.x = fminf(fmaxf(accf[i][0] * inv + add, 0.f), 6.f);
    o0.y = fminf(fmaxf(accf[i][1] * inv + add, 0.f), 6.f);
    o0.z = fminf(fmaxf(accf[i][2] * inv + add, 0.f), 6.f);
    o0.w = fminf(fmaxf(accf[i][3] * inv + add, 0.f), 6.f);
    o1.x = fminf(fmaxf(accf[i][4] * inv + add, 0.f), 6.f);
    o1.y = fminf(fmaxf(accf[i][5] * inv + add, 0.f), 6.f);
    o1.z = fminf(fmaxf(accf[i][6] * inv + add, 0.f), 6.f);
    o1.w = fminf(fmaxf(accf[i][7] * inv + add, 0.f), 6.f);
    *(float4*)dst = o0;
    *(float4*)(dst + 4) = o1;
  }
}

// ===================== host launcher ========================================
static float* symf(const void* s) {
  void* p = nullptr;
  cudaGetSymbolAddress(&p, s);
  return (float*)p;
}

extern "C" void kernel_launch(void* const* d_in, const int* in_sizes, int n_in,
                              void* d_out, int out_size) {
  const float* x      = (const float*)d_in[0];
  const float* down_w = (const float*)d_in[1];
  const float* down_b = (const float*)d_in[2];
  const float* up_w   = (const float*)d_in[3];
  const float* up_b   = (const float*)d_in[4];
  const float* wqkv_c = (const float*)d_in[5];
  const float* bqkv_c = (const float*)d_in[6];
  const float* wqkv_f = (const float*)d_in[7];
  const float* bqkv_f = (const float*)d_in[8];
  const float* dw_w   = (const float*)d_in[9];
  const float* bn1_g  = (const float*)d_in[10];
  const float* bn1_b  = (const float*)d_in[11];
  const float* bn1_m  = (const float*)d_in[12];
  const float* bn1_v  = (const float*)d_in[13];
  const float* pw_w   = (const float*)d_in[14];
  const float* bn2_g  = (const float*)d_in[15];
  const float* bn2_b  = (const float*)d_in[16];
  const float* bn2_m  = (const float*)d_in[17];
  const float* bn2_v  = (const float*)d_in[18];
  float* out = (float*)d_out;

  float* xd     = symf(g_xd);
  float* tok    = symf(g_tok);
  float* q      = symf(g_q);
  float* kk     = symf(g_kk);
  float* v      = symf(g_v);
  float* attn   = symf(g_attn);
  float* part   = symf(g_part);
  float* score  = symf(g_score);
  int*   topk   = (int*)symf(g_topk);
  float* aout   = symf(g_aout);
  float* coarse = symf(g_coarse);
  float* outf   = symf(g_outf);
  float* y1     = symf(g_y1);
  float* upw    = symf(g_upw);

  // ---- coarse branch ----
  k_repack_upw<<<4096, 256>>>(up_w, upw);
  k_conv_down<<<dim3(64, 2), 256>>>(x, down_w, down_b, xd);
  k_tokc<<<dim3(32, 16), 256>>>(xd, tok);
  k_qkv<<<dim3(3, 8, 32), 256>>>(tok, wqkv_c, bqkv_c, q, kk, v);
  k_qkT<<<dim3(8, 8, 32), 256>>>(q, kk, attn);
  k_softmax<<<dim3(1024, 32), 256>>>(attn);
  k_colsum_part<<<dim3(32, 8), 1024>>>(attn, part);
  k_colsum_red<<<32, 1024>>>(part, score);
  k_topk<<<32, 1024>>>(score, topk);
  k_av<<<dim3(1, 8, 32), 128>>>(attn, v, aout, 1);
  k_conv_up<<<dim3(64, 2, 4), 256>>>(aout, upw, up_b, coarse);

  // ---- fine branch ----
  k_gather<<<dim3(32, 16), 256>>>(coarse, topk, tok);
  k_qkv<<<dim3(3, 8, 32), 256>>>(tok, wqkv_f, bqkv_f, q, kk, v);
  k_qkT<<<dim3(8, 8, 32), 256>>>(q, kk, attn);
  k_softmax<<<dim3(1024, 32), 256>>>(attn);
  k_av<<<dim3(1, 8, 32), 128>>>(attn, v, outf, 0);
  k_scatter<<<dim3(32, 16), 256>>>(outf, topk, coarse);

  // ---- DWConv block ----
  k_dw<<<32768, 256>>>(coarse, dw_w, bn1_g, bn1_b, bn1_m, bn1_v, y1);
  k_pw<<<dim3(256, 2), 256>>>(y1, pw_w, bn2_g, bn2_b, bn2_m, bn2_v, out);
}

// round 9
// speedup vs baseline: 1.2366x; 1.2366x over previous
#include <cuda_runtime.h>
#include <cstddef>

typedef unsigned int uint32;

// ===================== problem constants =====================
// B=8, C=256, H=W=64, HD=64, NH=4 heads, BH=B*NH=32, N=1024 coarse tokens,
// KF=256 selected patches, PS=2.

// ===================== device scratch (no allocations allowed) =============
__device__ float g_xd[2097152];      // [8,256,32,32] downsampled
__device__ float g_tok[2097152];     // [32,1024,64] tokens (coarse, then fine)
__device__ float g_q[2097152];       // [32,1024,64] (q pre-scaled by 0.125)
__device__ float g_kk[2097152];      // [32,1024,64]
__device__ float g_v[2097152];       // [32,1024,64]
__device__ float g_attn[33554432];   // [32,1024,1024]
__device__ float g_part[262144];     // [32,8,1024] colsum partials
__device__ float g_score[32768];     // [32,1024]
__device__ int   g_topk[8192];       // [32,256]
__device__ float g_aout[2097152];    // [8,256,32,32] coarse attn out (image layout)
__device__ float g_coarse[8388608];  // [8,256,64,64]
__device__ float g_outf[2097152];    // [32,1024,64] fine attn out
__device__ float g_y1[8388608];      // [8,256,64,64] after dw+bn1+relu6
__device__ float g_upw[1048576];     // [4 parity][256 co][256 ci *4 taps]

// ===================== fp32 SIMT GEMM microkernel (R5 baseline) =============
// Tile: BM=128, BN=64, BK=16. 256 threads. Each thread: 8x4 outputs.

__device__ __forceinline__ void ldA_rowmajor(float (&As)[16][132],
    const float* __restrict__ A, int lda, int m0, int k0, int tid) {
  int m  = tid >> 1;             // 0..127
  int kq = (tid & 1) * 8;        // 0 or 8
  const float* src = A + (size_t)(m0 + m) * lda + k0 + kq;
  float4 x0 = *(const float4*)(src);
  float4 x1 = *(const float4*)(src + 4);
  As[kq + 0][m] = x0.x; As[kq + 1][m] = x0.y;
  As[kq + 2][m] = x0.z; As[kq + 3][m] = x0.w;
  As[kq + 4][m] = x1.x; As[kq + 5][m] = x1.y;
  As[kq + 6][m] = x1.z; As[kq + 7][m] = x1.w;
}

__device__ __forceinline__ void ldB_rowmajor(float (&Bs)[16][68],
    const float* __restrict__ Bm, int ldb, int k0, int n0, int tid) {
  int kk = tid >> 4;             // 0..15
  int nn = (tid & 15) * 4;       // 0..60
  float4 x = *(const float4*)(Bm + (size_t)(k0 + kk) * ldb + n0 + nn);
  *(float4*)&Bs[kk][nn] = x;
}

__device__ __forceinline__ void ldB_transposed(float (&Bs)[16][68],
    const float* __restrict__ Bm, int ldb, int k0, int n0, int tid) {
  int n  = tid >> 2;             // 0..63
  int kq = (tid & 3) * 4;        // 0..12
  float4 x = *(const float4*)(Bm + (size_t)(n0 + n) * ldb + k0 + kq);
  Bs[kq + 0][n] = x.x; Bs[kq + 1][n] = x.y;
  Bs[kq + 2][n] = x.z; Bs[kq + 3][n] = x.w;
}

__device__ __forceinline__ void fma_tile(const float (&As)[16][132],
    const float (&Bs)[16][68], float (&acc)[8][4], int tx, int ty) {
#pragma unroll
  for (int kk = 0; kk < 16; kk++) {
    float4 a0 = *(const float4*)&As[kk][ty * 8];
    float4 a1 = *(const float4*)&As[kk][ty * 8 + 4];
    float4 b4 = *(const float4*)&Bs[kk][tx * 4];
    float av[8] = {a0.x, a0.y, a0.z, a0.w, a1.x, a1.y, a1.z, a1.w};
    float bv[4] = {b4.x, b4.y, b4.z, b4.w};
#pragma unroll
    for (int i = 0; i < 8; i++)
#pragma unroll
      for (int j = 0; j < 4; j++) acc[i][j] += av[i] * bv[j];
  }
}

// ===================== tf32 mma.sync primitives =============================
__device__ __forceinline__ uint32 tf32cvt(float x) {
  uint32 r;
  asm("cvt.rna.tf32.f32 %0, %1;" : "=r"(r) : "f"(x));
  return r;
}
__device__ __forceinline__ void mma_tf32(float (&c)[4], const uint32 (&a)[4],
                                         const uint32 (&b)[2]) {
  asm volatile(
      "mma.sync.aligned.m16n8k8.row.col.f32.tf32.tf32.f32 "
      "{%0,%1,%2,%3}, {%4,%5,%6,%7}, {%8,%9}, {%0,%1,%2,%3};"
      : "+f"(c[0]), "+f"(c[1]), "+f"(c[2]), "+f"(c[3])
      : "r"(a[0]), "r"(a[1]), "r"(a[2]), "r"(a[3]), "r"(b[0]), "r"(b[1]));
}

// tf32 A staging: As[k][m] bits, BM=128, BK=16, row-major fp32 source.
__device__ __forceinline__ void ldA_tf32(uint32 (&As)[16][132],
    const float* __restrict__ A, int lda, int m0, int k0, int tid) {
  int m  = tid >> 1;
  int kq = (tid & 1) * 8;
  const float* src = A + (size_t)(m0 + m) * lda + k0 + kq;
  float4 x0 = *(const float4*)(src);
  float4 x1 = *(const float4*)(src + 4);
  As[kq + 0][m] = tf32cvt(x0.x); As[kq + 1][m] = tf32cvt(x0.y);
  As[kq + 2][m] = tf32cvt(x0.z); As[kq + 3][m] = tf32cvt(x0.w);
  As[kq + 4][m] = tf32cvt(x1.x); As[kq + 5][m] = tf32cvt(x1.y);
  As[kq + 6][m] = tf32cvt(x1.z); As[kq + 7][m] = tf32cvt(x1.w);
}

// Warp-level 64x32 tf32 tile over block tile 128x128:
// 8 warps = 2 (m) x 4 (n). Per warp: 4 mi x 4 ni m16n8 frags, 2 k-steps of 8.
__device__ __forceinline__ void mma_tile_tf32(const uint32 (&As)[16][132],
    const uint32 (&Bs)[16][132], float (&c)[4][4][4], int lane, int wm, int wn) {
  int g = lane >> 2, t = lane & 3;
#pragma unroll
  for (int ks = 0; ks < 2; ks++) {
    int kb = ks * 8;
    uint32 a[4][4];
#pragma unroll
    for (int mi = 0; mi < 4; mi++) {
      int mr = wm + mi * 16 + g;
      a[mi][0] = As[kb + t][mr];
      a[mi][1] = As[kb + t][mr + 8];
      a[mi][2] = As[kb + t + 4][mr];
      a[mi][3] = As[kb + t + 4][mr + 8];
    }
    uint32 b[4][2];
#pragma unroll
    for (int ni = 0; ni < 4; ni++) {
      int nc = wn + ni * 8 + g;
      b[ni][0] = Bs[kb + t][nc];
      b[ni][1] = Bs[kb + t + 4][nc];
    }
#pragma unroll
    for (int mi = 0; mi < 4; mi++)
#pragma unroll
      for (int ni = 0; ni < 4; ni++) mma_tf32(c[mi][ni], a[mi], b[ni]);
  }
}

// ===================== 0) repack ConvTranspose weights ======================
__global__ void k_repack_upw(const float* __restrict__ upw, float* __restrict__ dst) {
  int idx = blockIdx.x * 256 + threadIdx.x;   // 1048576
  int t  = idx & 3;
  int ci = (idx >> 2) & 255;
  int co = (idx >> 10) & 255;
  int pc = idx >> 18;
  int py = pc >> 1, px = pc & 1;
  int ky = ((py + 1) & 1) + ((t >> 1) << 1);
  int kx = ((px + 1) & 1) + ((t & 1) << 1);
  dst[idx] = upw[((ci * 256 + co) * 4 + ky) * 4 + kx];
}

// ===================== 1) conv 4x4 stride2 pad1 (fp32, topk-critical) =======
__global__ void __launch_bounds__(256) k_conv_down(const float* __restrict__ x,
    const float* __restrict__ w, const float* __restrict__ bias,
    float* __restrict__ out) {
  __shared__ float As[16][132];
  __shared__ float Bs[16][68];
  float acc[8][4] = {};
  int tid = threadIdx.x, tx = tid & 15, ty = tid >> 4;
  int m0 = blockIdx.y * 128, n0 = blockIdx.x * 64;
  int lkk = tid >> 4, lnn = (tid & 15) * 4;
  for (int k0 = 0; k0 < 4096; k0 += 16) {
    ldA_rowmajor(As, w, 4096, m0, k0, tid);
    {
      int k = k0 + lkk;
      int ci = k >> 4, ky = (k >> 2) & 3, kx = k & 3;
#pragma unroll
      for (int j = 0; j < 4; j++) {
        int n = n0 + lnn + j;
        int b = n >> 10, rem = n & 1023;
        int oy = rem >> 5, ox = rem & 31;
        int iy = 2 * oy + ky - 1, ix = 2 * ox + kx - 1;
        float vv = 0.f;
        if ((unsigned)iy < 64u && (unsigned)ix < 64u)
          vv = x[(((b << 8) + ci) << 12) + (iy << 6) + ix];
        Bs[lkk][lnn + j] = vv;
      }
    }
    __syncthreads();
    fma_tile(As, Bs, acc, tx, ty);
    __syncthreads();
  }
  int n = n0 + tx * 4;
  int b = n >> 10, rem = n & 1023;
#pragma unroll
  for (int i = 0; i < 8; i++) {
    int m = m0 + ty * 8 + i;
    float bi = bias[m];
    float4 o = make_float4(acc[i][0] + bi, acc[i][1] + bi,
                           acc[i][2] + bi, acc[i][3] + bi);
    *(float4*)&out[(((b << 8) + m) << 10) + rem] = o;
  }
}

// ===================== 2) image -> token transpose (coarse) =================
__global__ void k_tokc(const float* __restrict__ xd, float* __restrict__ tok) {
  __shared__ float s[64][65];
  int bh = blockIdx.x, nch = blockIdx.y;   // 32 x 16
  int b = bh >> 2, h = bh & 3;
  int tid = threadIdx.x;
  int n0 = nch * 64;
#pragma unroll
  for (int i = 0; i < 16; i++) {
    int lin = i * 256 + tid;
    int d = lin >> 6, nn = lin & 63;
    s[d][nn] = xd[(((b << 8) + (h << 6) + d) << 10) + n0 + nn];
  }
  __syncthreads();
#pragma unroll
  for (int i = 0; i < 16; i++) {
    int lin = i * 256 + tid;
    int nn = lin >> 6, d = lin & 63;
    tok[((size_t)bh << 16) + ((size_t)(n0 + nn) << 6) + d] = s[d][nn];
  }
}

// ===================== 3) QKV GEMM: [1024,64] @ [64,192] + bias =============
__global__ void __launch_bounds__(256) k_qkv(const float* __restrict__ tok,
    const float* __restrict__ wqkv, const float* __restrict__ bqkv,
    float* __restrict__ q, float* __restrict__ kmat, float* __restrict__ v) {
  __shared__ float As[16][132];
  __shared__ float Bs[16][68];
  float acc[8][4] = {};
  int tid = threadIdx.x, tx = tid & 15, ty = tid >> 4;
  int bh = blockIdx.z;
  int m0 = blockIdx.y * 128, n0 = blockIdx.x * 64;
  const float* A = tok + ((size_t)bh << 16);
  for (int k0 = 0; k0 < 64; k0 += 16) {
    ldA_rowmajor(As, A, 64, m0, k0, tid);
    ldB_rowmajor(Bs, wqkv, 192, k0, n0, tid);
    __syncthreads();
    fma_tile(As, Bs, acc, tx, ty);
    __syncthreads();
  }
  int sec = n0 >> 6;                               // 0:q 1:k 2:v
  float* dst = (sec == 0) ? q : ((sec == 1) ? kmat : v);
  float mul = (sec == 0) ? 0.125f : 1.0f;          // HD^-0.5 folded into q
  int d0 = tx * 4;
#pragma unroll
  for (int i = 0; i < 8; i++) {
    int m = m0 + ty * 8 + i;
    float4 o;
    o.x = (acc[i][0] + bqkv[n0 + d0 + 0]) * mul;
    o.y = (acc[i][1] + bqkv[n0 + d0 + 1]) * mul;
    o.z = (acc[i][2] + bqkv[n0 + d0 + 2]) * mul;
    o.w = (acc[i][3] + bqkv[n0 + d0 + 3]) * mul;
    *(float4*)&dst[((size_t)bh << 16) + ((size_t)m << 6) + d0] = o;
  }
}

// ===================== 4) S = q @ k^T (fp32, topk-critical) =================
__global__ void __launch_bounds__(256) k_qkT(const float* __restrict__ q,
    const float* __restrict__ kmat, float* __restrict__ attn) {
  __shared__ float As[16][132];
  __shared__ float Bs[16][68];
  float acc[8][4] = {};
  int tid = threadIdx.x, tx = tid & 15, ty = tid >> 4;
  int bh = blockIdx.z, m0 = blockIdx.y * 128, n0 = blockIdx.x * 64;
  const float* A  = q    + ((size_t)bh << 16);
  const float* Bm = kmat + ((size_t)bh << 16);
  for (int k0 = 0; k0 < 64; k0 += 16) {
    ldA_rowmajor(As, A, 64, m0, k0, tid);
    ldB_transposed(Bs, Bm, 64, k0, n0, tid);
    __syncthreads();
    fma_tile(As, Bs, acc, tx, ty);
    __syncthreads();
  }
  float* out = attn + ((size_t)bh << 20);
#pragma unroll
  for (int i = 0; i < 8; i++) {
    int m = m0 + ty * 8 + i;
    float4 o = make_float4(acc[i][0], acc[i][1], acc[i][2], acc[i][3]);
    *(float4*)&out[((size_t)m << 10) + n0 + tx * 4] = o;
  }
}

// ===================== 5) row softmax in place ==============================
__global__ void __launch_bounds__(256) k_softmax(float* __restrict__ attn) {
  int row = blockIdx.x, bh = blockIdx.y;
  float* p = attn + ((size_t)bh << 20) + ((size_t)row << 10);
  int tid = threadIdx.x;
  float4 v = *(float4*)&p[tid * 4];
  __shared__ float red[256];
  float mx = fmaxf(fmaxf(v.x, v.y), fmaxf(v.z, v.w));
  red[tid] = mx;
  __syncthreads();
  for (int s = 128; s > 0; s >>= 1) {
    if (tid < s) red[tid] = fmaxf(red[tid], red[tid + s]);
    __syncthreads();
  }
  mx = red[0];
  __syncthreads();
  v.x = __expf(v.x - mx); v.y = __expf(v.y - mx);
  v.z = __expf(v.z - mx); v.w = __expf(v.w - mx);
  red[tid] = (v.x + v.y) + (v.z + v.w);
  __syncthreads();
  for (int s = 128; s > 0; s >>= 1) {
    if (tid < s) red[tid] += red[tid + s];
    __syncthreads();
  }
  float inv = 1.0f / red[0];
  v.x *= inv; v.y *= inv; v.z *= inv; v.w *= inv;
  *(float4*)&p[tid * 4] = v;
}

// ===================== 6) column sums (deterministic 2-phase) ===============
__global__ void k_colsum_part(const float* __restrict__ attn, float* __restrict__ part) {
  int bh = blockIdx.x, ny = blockIdx.y, m = threadIdx.x;  // 32 x 8, 1024 thr
  const float* p = attn + ((size_t)bh << 20) + ((size_t)(ny * 128) << 10) + m;
  float a0 = 0, a1 = 0, a2 = 0, a3 = 0;
  for (int n = 0; n < 128; n += 4) {
    a0 += p[(size_t)(n + 0) << 10];
    a1 += p[(size_t)(n + 1) << 10];
    a2 += p[(size_t)(n + 2) << 10];
    a3 += p[(size_t)(n + 3) << 10];
  }
  part[(bh * 8 + ny) * 1024 + m] = (a0 + a1) + (a2 + a3);
}
__global__ void k_colsum_red(const float* __restrict__ part, float* __restrict__ score) {
  int bh = blockIdx.x, m = threadIdx.x;
  float a = 0;
#pragma unroll
  for (int i = 0; i < 8; i++) a += part[(bh * 8 + i) * 1024 + m];
  score[bh * 1024 + m] = a;
}

// ===================== 7) top-256 by rank (matches lax.top_k order) =========
__global__ void k_topk(const float* __restrict__ score, int* __restrict__ topk) {
  int bh = blockIdx.x;
  __shared__ float s[1024];
  int tid = threadIdx.x;   // 1024
  s[tid] = score[bh * 1024 + tid];
  __syncthreads();
  float mine = s[tid];
  int rank = 0;
  for (int j = 0; j < 1024; j++) {
    float o = s[j];
    rank += (o > mine) || (o == mine && j < tid);
  }
  if (rank < 256) topk[bh * 256 + rank] = tid;
}

// ===================== 8) out = attn @ v  (fp32 8x4 path) ===================
// mode 0: write [bh][m][64] row-major (fine). mode 1: image layout aout.
__global__ void __launch_bounds__(256) k_av(const float* __restrict__ attn,
    const float* __restrict__ v, float* __restrict__ out, int mode) {
  __shared__ float As[16][132];
  __shared__ float Bs[16][68];
  float acc[8][4] = {};
  int tid = threadIdx.x, tx = tid & 15, ty = tid >> 4;
  int bh = blockIdx.z, m0 = blockIdx.y * 128;     // N=64 -> single n block
  const float* A  = attn + ((size_t)bh << 20);
  const float* Bm = v    + ((size_t)bh << 16);
  for (int k0 = 0; k0 < 1024; k0 += 16) {
    ldA_rowmajor(As, A, 1024, m0, k0, tid);
    ldB_rowmajor(Bs, Bm, 64, k0, 0, tid);
    __syncthreads();
    fma_tile(As, Bs, acc, tx, ty);
    __syncthreads();
  }
  if (mode == 0) {
    float* dst = out + ((size_t)bh << 16);
#pragma unroll
    for (int i = 0; i < 8; i++) {
      int m = m0 + ty * 8 + i;
      float4 o = make_float4(acc[i][0], acc[i][1], acc[i][2], acc[i][3]);
      *(float4*)&dst[((size_t)m << 6) + tx * 4] = o;
    }
  } else {
    int b = bh >> 2, h = bh & 3;
#pragma unroll
    for (int i = 0; i < 8; i++) {
      int m = m0 + ty * 8 + i;
#pragma unroll
      for (int j = 0; j < 4; j++) {
        int d = tx * 4 + j;
        out[(((b << 8) + (h << 6) + d) << 10) + m] = acc[i][j];
      }
    }
  }
}

// ===================== 9) ConvTranspose 4x4 s2 p1 — tf32 tensor core ========
// M=256 co, N=8192 (b, 32x32 half-res), K=1024 (ci*4 + tap). BM=128, BN=128.
__global__ void __launch_bounds__(256) k_conv_up_t(const float* __restrict__ ain,
    const float* __restrict__ wre, const float* __restrict__ bias,
    float* __restrict__ out) {
  __shared__ uint32 As[16][132];
  __shared__ uint32 Bs[16][132];
  float c[4][4][4] = {};
  int tid = threadIdx.x, lane = tid & 31, wid = tid >> 5;
  int wm = (wid & 1) * 64, wn = (wid >> 1) * 32;
  int m0 = blockIdx.y * 128, n0 = blockIdx.x * 128;
  int pc = blockIdx.z;
  int py = pc >> 1, px = pc & 1;
  const float* A = wre + (size_t)pc * 262144;
  int lkk = tid >> 4, lnn = (tid & 15) * 8;
  int dy0 = (py + 1) >> 1, dx0 = (px + 1) >> 1;
  int bimg = n0 >> 10, rem0 = (n0 & 1023) + lnn;
  const float* ab = ain + ((size_t)bimg << 18);
  for (int k0 = 0; k0 < 1024; k0 += 16) {
    ldA_tf32(As, A, 1024, m0, k0, tid);
    {
      int k = k0 + lkk;
      int ci = k >> 2, t = k & 3;
      int dy = dy0 - (t >> 1), dx = dx0 - (t & 1);
      const float* ac = ab + ((size_t)ci << 10);
#pragma unroll
      for (int j = 0; j < 8; j++) {
        int rem = rem0 + j;
        int iy = (rem >> 5) + dy, ix = (rem & 31) + dx;
        float vv = 0.f;
        if ((unsigned)iy < 32u && (unsigned)ix < 32u) vv = ac[(iy << 5) + ix];
        Bs[lkk][lnn + j] = tf32cvt(vv);
      }
    }
    __syncthreads();
    mma_tile_tf32(As, Bs, c, lane, wm, wn);
    __syncthreads();
  }
  int g = lane >> 2, t2 = (lane & 3) * 2;
#pragma unroll
  for (int mi = 0; mi < 4; mi++) {
    int m = m0 + wm + mi * 16 + g;
    float bi0 = bias[m], bi1 = bias[m + 8];
    float* base0 = &out[(((bimg << 8) + m) << 12)];
    float* base1 = base0 + (8 << 12);
#pragma unroll
    for (int ni = 0; ni < 4; ni++) {
      int ln = wn + ni * 8 + t2;
      int rem = (n0 & 1023) + ln;
      int oy2 = rem >> 5, ox2 = rem & 31;
      int off = ((2 * oy2 + py) << 6) + 2 * ox2 + px;
      base0[off]     = c[mi][ni][0] + bi0;
      base0[off + 2] = c[mi][ni][1] + bi0;
      base1[off]     = c[mi][ni][2] + bi1;
      base1[off + 2] = c[mi][ni][3] + bi1;
    }
  }
}

// ===================== 10) gather fine tokens ===============================
__global__ void k_gather(const float* __restrict__ coarse, const int* __restrict__ topk,
                         float* __restrict__ tok) {
  int bh = blockIdx.x, chunk = blockIdx.y;   // 32 x 16
  int tid = threadIdx.x;
  int d = tid & 63;
  int b = bh >> 2, h = bh & 3;
#pragma unroll
  for (int i = 0; i < 16; i++) {
    int j = chunk * 64 + (tid >> 6) + i * 4;  // token 0..1023
    int p = j >> 2, l = j & 3;
    int qq = topk[bh * 256 + p];
    int py = ((qq >> 5) << 1) + (l >> 1);
    int px = ((qq & 31) << 1) + (l & 1);
    tok[((size_t)bh << 16) + ((size_t)j << 6) + d] =
        coarse[(((b << 8) + (h << 6) + d) << 12) + (py << 6) + px];
  }
}

// ===================== 11) scatter-add fine outputs into coarse =============
__global__ void k_scatter(const float* __restrict__ outf, const int* __restrict__ topk,
                          float* __restrict__ coarse) {
  int bh = blockIdx.x, chunk = blockIdx.y;
  int tid = threadIdx.x;
  int d = tid & 63;
  int b = bh >> 2, h = bh & 3;
#pragma unroll
  for (int i = 0; i < 16; i++) {
    int j = chunk * 64 + (tid >> 6) + i * 4;
    int p = j >> 2, l = j & 3;
    int qq = topk[bh * 256 + p];
    int py = ((qq >> 5) << 1) + (l >> 1);
    int px = ((qq & 31) << 1) + (l & 1);
    coarse[(((b << 8) + (h << 6) + d) << 12) + (py << 6) + px] +=
        outf[((size_t)bh << 16) + ((size_t)j << 6) + d];
  }
}

// ===================== 12) depthwise 3x3 + BN1 + ReLU6 ======================
__global__ void k_dw(const float* __restrict__ y, const float* __restrict__ w,
    const float* __restrict__ g, const float* __restrict__ bb,
    const float* __restrict__ mm, const float* __restrict__ vv,
    float* __restrict__ out) {
  int idx = blockIdx.x * 256 + threadIdx.x;   // 8*256*4096
  int x = idx & 63, yy = (idx >> 6) & 63, c = (idx >> 12) & 255, b = idx >> 20;
  const float* base = y + ((size_t)((b << 8) + c) << 12);
  float acc = 0.f;
#pragma unroll
  for (int ky = 0; ky < 3; ky++) {
    int iy = yy + ky - 1;
    if ((unsigned)iy >= 64u) continue;
#pragma unroll
    for (int kx = 0; kx < 3; kx++) {
      int ix = x + kx - 1;
      if ((unsigned)ix >= 64u) continue;
      acc += w[c * 9 + ky * 3 + kx] * base[(iy << 6) + ix];
    }
  }
  float inv = g[c] * rsqrtf(vv[c] + 1e-5f);
  float val = acc * inv + (bb[c] - mm[c] * inv);
  out[idx] = fminf(fmaxf(val, 0.f), 6.f);
}

// ===================== 13) pointwise 1x1 + BN2 + ReLU6 — tf32 tensor core ===
// M=256 co, N=32768 (b, 64x64), K=256. BM=128, BN=128.
__global__ void __launch_bounds__(256) k_pw_t(const float* __restrict__ y1,
    const float* __restrict__ w, const float* __restrict__ bn_g,
    const float* __restrict__ bn_b, const float* __restrict__ bn_m,
    const float* __restrict__ bn_v, float* __restrict__ out) {
  __shared__ uint32 As[16][132];
  __shared__ uint32 Bs[16][132];
  float c[4][4][4] = {};
  int tid = threadIdx.x, lane = tid & 31, wid = tid >> 5;
  int wm = (wid & 1) * 64, wn = (wid >> 1) * 32;
  int m0 = blockIdx.y * 128, n0 = blockIdx.x * 128;
  int lkk = tid >> 4, lnn = (tid & 15) * 8;
  int bB = n0 >> 12, remB = (n0 & 4095) + lnn;
  const float* yb = y1 + ((size_t)bB << 20);
  for (int k0 = 0; k0 < 256; k0 += 16) {
    ldA_tf32(As, w, 256, m0, k0, tid);
    {
      const float* src = yb + ((size_t)(k0 + lkk) << 12) + remB;
      float4 x0 = *(const float4*)(src);
      float4 x1 = *(const float4*)(src + 4);
      Bs[lkk][lnn + 0] = tf32cvt(x0.x); Bs[lkk][lnn + 1] = tf32cvt(x0.y);
      Bs[lkk][lnn + 2] = tf32cvt(x0.z); Bs[lkk][lnn + 3] = tf32cvt(x0.w);
      Bs[lkk][lnn + 4] = tf32cvt(x1.x); Bs[lkk][lnn + 5] = tf32cvt(x1.y);
      Bs[lkk][lnn + 6] = tf32cvt(x1.z); Bs[lkk][lnn + 7] = tf32cvt(x1.w);
    }
    __syncthreads();
    mma_tile_tf32(As, Bs, c, lane, wm, wn);
    __syncthreads();
  }
  int g = lane >> 2, t2 = (lane & 3) * 2;
#pragma unroll
  for (int mi = 0; mi < 4; mi++) {
    int m = m0 + wm + mi * 16 + g;
    float inv0 = bn_g[m] * rsqrtf(bn_v[m] + 1e-5f);
    float add0 = bn_b[m] - bn_m[m] * inv0;
    float inv1 = bn_g[m + 8] * rsqrtf(bn_v[m + 8] + 1e-5f);
    float add1 = bn_b[m + 8] - bn_m[m + 8] * inv1;
    float* base0 = &out[(((size_t)(bB << 8) + m) << 12)];
    float* base1 = base0 + (8 << 12);
#pragma unroll
    for (int ni = 0; ni < 4; ni++) {
      int rem = (n0 & 4095) + wn + ni * 8 + t2;
      float2 o0, o1;
      o0.x = fminf(fmaxf(c[mi][ni][0] * inv0 + add0, 0.f), 6.f);
      o0.y = fminf(fmaxf(c[mi][ni][1] * inv0 + add0, 0.f), 6.f);
      o1.x = fminf(fmaxf(c[mi][ni][2] * inv1 + add1, 0.f), 6.f);
      o1.y = fminf(fmaxf(c[mi][ni][3] * inv1 + add1, 0.f), 6.f);
      *(float2*)&base0[rem] = o0;
      *(float2*)&base1[rem] = o1;
    }
  }
}

// ===================== host launcher ========================================
static float* symf(const void* s) {
  void* p = nullptr;
  cudaGetSymbolAddress(&p, s);
  return (float*)p;
}

extern "C" void kernel_launch(void* const* d_in, const int* in_sizes, int n_in,
                              void* d_out, int out_size) {
  const float* x      = (const float*)d_in[0];
  const float* down_w = (const float*)d_in[1];
  const float* down_b = (const float*)d_in[2];
  const float* up_w   = (const float*)d_in[3];
  const float* up_b   = (const float*)d_in[4];
  const float* wqkv_c = (const float*)d_in[5];
  const float* bqkv_c = (const float*)d_in[6];
  const float* wqkv_f = (const float*)d_in[7];
  const float* bqkv_f = (const float*)d_in[8];
  const float* dw_w   = (const float*)d_in[9];
  const float* bn1_g  = (const float*)d_in[10];
  const float* bn1_b  = (const float*)d_in[11];
  const float* bn1_m  = (const float*)d_in[12];
  const float* bn1_v  = (const float*)d_in[13];
  const float* pw_w   = (const float*)d_in[14];
  const float* bn2_g  = (const float*)d_in[15];
  const float* bn2_b  = (const float*)d_in[16];
  const float* bn2_m  = (const float*)d_in[17];
  const float* bn2_v  = (const float*)d_in[18];
  float* out = (float*)d_out;

  float* xd     = symf(g_xd);
  float* tok    = symf(g_tok);
  float* q      = symf(g_q);
  float* kk     = symf(g_kk);
  float* v      = symf(g_v);
  float* attn   = symf(g_attn);
  float* part   = symf(g_part);
  float* score  = symf(g_score);
  int*   topk   = (int*)symf(g_topk);
  float* aout   = symf(g_aout);
  float* coarse = symf(g_coarse);
  float* outf   = symf(g_outf);
  float* y1     = symf(g_y1);
  float* upw    = symf(g_upw);

  // ---- coarse branch ----
  k_repack_upw<<<4096, 256>>>(up_w, upw);
  k_conv_down<<<dim3(128, 2), 256>>>(x, down_w, down_b, xd);
  k_tokc<<<dim3(32, 16), 256>>>(xd, tok);
  k_qkv<<<dim3(3, 8, 32), 256>>>(tok, wqkv_c, bqkv_c, q, kk, v);
  k_qkT<<<dim3(16, 8, 32), 256>>>(q, kk, attn);
  k_softmax<<<dim3(1024, 32), 256>>>(attn);
  k_colsum_part<<<dim3(32, 8), 1024>>>(attn, part);
  k_colsum_red<<<32, 1024>>>(part, score);
  k_topk<<<32, 1024>>>(score, topk);
  k_av<<<dim3(1, 8, 32), 256>>>(attn, v, aout, 1);
  k_conv_up_t<<<dim3(64, 2, 4), 256>>>(aout, upw, up_b, coarse);

  // ---- fine branch ----
  k_gather<<<dim3(32, 16), 256>>>(coarse, topk, tok);
  k_qkv<<<dim3(3, 8, 32), 256>>>(tok, wqkv_f, bqkv_f, q, kk, v);
  k_qkT<<<dim3(16, 8, 32), 256>>>(q, kk, attn);
  k_softmax<<<dim3(1024, 32), 256>>>(attn);
  k_av<<<dim3(1, 8, 32), 256>>>(attn, v, outf, 0);
  k_scatter<<<dim3(32, 16), 256>>>(outf, topk, coarse);

  // ---- DWConv block ----
  k_dw<<<32768, 256>>>(coarse, dw_w, bn1_g, bn1_b, bn1_m, bn1_v, y1);
  k_pw_t<<<dim3(256, 2), 256>>>(y1, pw_w, bn2_g, bn2_b, bn2_m, bn2_v, out);
}

// round 10
// speedup vs baseline: 1.3356x; 1.0801x over previous
#include <cuda_runtime.h>
#include <cstddef>

typedef unsigned int uint32;

// ===================== problem constants =====================
// B=8, C=256, H=W=64, HD=64, NH=4 heads, BH=B*NH=32, N=1024 coarse tokens,
// KF=256 selected patches, PS=2.

// ===================== device scratch (no allocations allowed) =============
__device__ float g_xd[2097152];      // [8,256,32,32] downsampled
__device__ float g_tok[2097152];     // [32,1024,64] tokens (coarse, then fine)
__device__ float g_q[2097152];       // [32,1024,64] (q pre-scaled by 0.125)
__device__ float g_kk[2097152];      // [32,1024,64]
__device__ float g_v[2097152];       // [32,1024,64]
__device__ float g_attn[33554432];   // [32,1024,1024]
__device__ float g_part[262144];     // [32,8,1024] colsum partials
__device__ float g_score[32768];     // [32,1024]
__device__ int   g_topk[8192];       // [32,256]
__device__ float g_aout[2097152];    // [8,256,32,32] coarse attn out (image layout)
__device__ float g_coarse[8388608];  // [8,256,64,64]
__device__ float g_outf[2097152];    // [32,1024,64] fine attn out
__device__ float g_y1[8388608];      // [8,256,64,64] after dw+bn1+relu6
__device__ float g_upw[1048576];     // [4 parity][256 co][256 ci *4 taps]

// ===================== fp32 SIMT GEMM microkernel ===========================
// Tile: BM=128, BN=64, BK=16. 256 threads. Each thread: 8x4 outputs.

__device__ __forceinline__ void ldA_rowmajor(float (&As)[16][132],
    const float* __restrict__ A, int lda, int m0, int k0, int tid) {
  int m  = tid >> 1;             // 0..127
  int kq = (tid & 1) * 8;        // 0 or 8
  const float* src = A + (size_t)(m0 + m) * lda + k0 + kq;
  float4 x0 = *(const float4*)(src);
  float4 x1 = *(const float4*)(src + 4);
  As[kq + 0][m] = x0.x; As[kq + 1][m] = x0.y;
  As[kq + 2][m] = x0.z; As[kq + 3][m] = x0.w;
  As[kq + 4][m] = x1.x; As[kq + 5][m] = x1.y;
  As[kq + 6][m] = x1.z; As[kq + 7][m] = x1.w;
}

__device__ __forceinline__ void ldB_rowmajor(float (&Bs)[16][68],
    const float* __restrict__ Bm, int ldb, int k0, int n0, int tid) {
  int kk = tid >> 4;             // 0..15
  int nn = (tid & 15) * 4;       // 0..60
  float4 x = *(const float4*)(Bm + (size_t)(k0 + kk) * ldb + n0 + nn);
  *(float4*)&Bs[kk][nn] = x;
}

__device__ __forceinline__ void ldB_transposed(float (&Bs)[16][68],
    const float* __restrict__ Bm, int ldb, int k0, int n0, int tid) {
  int n  = tid >> 2;             // 0..63
  int kq = (tid & 3) * 4;        // 0..12
  float4 x = *(const float4*)(Bm + (size_t)(n0 + n) * ldb + k0 + kq);
  Bs[kq + 0][n] = x.x; Bs[kq + 1][n] = x.y;
  Bs[kq + 2][n] = x.z; Bs[kq + 3][n] = x.w;
}

__device__ __forceinline__ void fma_tile(const float (&As)[16][132],
    const float (&Bs)[16][68], float (&acc)[8][4], int tx, int ty) {
#pragma unroll
  for (int kk = 0; kk < 16; kk++) {
    float4 a0 = *(const float4*)&As[kk][ty * 8];
    float4 a1 = *(const float4*)&As[kk][ty * 8 + 4];
    float4 b4 = *(const float4*)&Bs[kk][tx * 4];
    float av[8] = {a0.x, a0.y, a0.z, a0.w, a1.x, a1.y, a1.z, a1.w};
    float bv[4] = {b4.x, b4.y, b4.z, b4.w};
#pragma unroll
    for (int i = 0; i < 8; i++)
#pragma unroll
      for (int j = 0; j < 4; j++) acc[i][j] += av[i] * bv[j];
  }
}

// ===================== tf32 mma.sync primitives =============================
__device__ __forceinline__ uint32 tf32cvt(float x) {
  uint32 r;
  asm("cvt.rna.tf32.f32 %0, %1;" : "=r"(r) : "f"(x));
  return r;
}
__device__ __forceinline__ void mma_tf32(float (&c)[4], const uint32 (&a)[4],
                                         const uint32 (&b)[2]) {
  asm volatile(
      "mma.sync.aligned.m16n8k8.row.col.f32.tf32.tf32.f32 "
      "{%0,%1,%2,%3}, {%4,%5,%6,%7}, {%8,%9}, {%0,%1,%2,%3};"
      : "+f"(c[0]), "+f"(c[1]), "+f"(c[2]), "+f"(c[3])
      : "r"(a[0]), "r"(a[1]), "r"(a[2]), "r"(a[3]), "r"(b[0]), "r"(b[1]));
}

// tf32 A staging: As[k][m] bits, BM=128, BK=16, row-major fp32 source.
__device__ __forceinline__ void ldA_tf32(uint32 (&As)[16][132],
    const float* __restrict__ A, int lda, int m0, int k0, int tid) {
  int m  = tid >> 1;
  int kq = (tid & 1) * 8;
  const float* src = A + (size_t)(m0 + m) * lda + k0 + kq;
  float4 x0 = *(const float4*)(src);
  float4 x1 = *(const float4*)(src + 4);
  As[kq + 0][m] = tf32cvt(x0.x); As[kq + 1][m] = tf32cvt(x0.y);
  As[kq + 2][m] = tf32cvt(x0.z); As[kq + 3][m] = tf32cvt(x0.w);
  As[kq + 4][m] = tf32cvt(x1.x); As[kq + 5][m] = tf32cvt(x1.y);
  As[kq + 6][m] = tf32cvt(x1.z); As[kq + 7][m] = tf32cvt(x1.w);
}

// tf32 transposed B staging: Bs[k][n] = Bm[n0+n][k0+k], BN=128, BK=16.
__device__ __forceinline__ void ldB_t_tf32(uint32 (&Bs)[16][132],
    const float* __restrict__ Bm, int ldb, int k0, int n0, int tid) {
  int n  = tid >> 1;
  int kq = (tid & 1) * 8;
  const float* src = Bm + (size_t)(n0 + n) * ldb + k0 + kq;
  float4 x0 = *(const float4*)(src);
  float4 x1 = *(const float4*)(src + 4);
  Bs[kq + 0][n] = tf32cvt(x0.x); Bs[kq + 1][n] = tf32cvt(x0.y);
  Bs[kq + 2][n] = tf32cvt(x0.z); Bs[kq + 3][n] = tf32cvt(x0.w);
  Bs[kq + 4][n] = tf32cvt(x1.x); Bs[kq + 5][n] = tf32cvt(x1.y);
  Bs[kq + 6][n] = tf32cvt(x1.z); Bs[kq + 7][n] = tf32cvt(x1.w);
}

// Warp-level 64x32 tf32 tile over block tile 128x128 (8 warps = 2m x 4n).
__device__ __forceinline__ void mma_tile_tf32(const uint32 (&As)[16][132],
    const uint32 (&Bs)[16][132], float (&c)[4][4][4], int lane, int wm, int wn) {
  int g = lane >> 2, t = lane & 3;
#pragma unroll
  for (int ks = 0; ks < 2; ks++) {
    int kb = ks * 8;
    uint32 a[4][4];
#pragma unroll
    for (int mi = 0; mi < 4; mi++) {
      int mr = wm + mi * 16 + g;
      a[mi][0] = As[kb + t][mr];
      a[mi][1] = As[kb + t][mr + 8];
      a[mi][2] = As[kb + t + 4][mr];
      a[mi][3] = As[kb + t + 4][mr + 8];
    }
    uint32 b[4][2];
#pragma unroll
    for (int ni = 0; ni < 4; ni++) {
      int nc = wn + ni * 8 + g;
      b[ni][0] = Bs[kb + t][nc];
      b[ni][1] = Bs[kb + t + 4][nc];
    }
#pragma unroll
    for (int mi = 0; mi < 4; mi++)
#pragma unroll
      for (int ni = 0; ni < 4; ni++) mma_tf32(c[mi][ni], a[mi], b[ni]);
  }
}

// Warp-level 32x32 tf32 tile over block tile 128x64 (8 warps = 4m x 2n).
__device__ __forceinline__ void mma_tile_tf32_32(const uint32 (&As)[16][132],
    const uint32 (&Bs)[16][68], float (&c)[2][4][4], int lane, int wm, int wn) {
  int g = lane >> 2, t = lane & 3;
#pragma unroll
  for (int ks = 0; ks < 2; ks++) {
    int kb = ks * 8;
    uint32 a[2][4];
#pragma unroll
    for (int mi = 0; mi < 2; mi++) {
      int mr = wm + mi * 16 + g;
      a[mi][0] = As[kb + t][mr];
      a[mi][1] = As[kb + t][mr + 8];
      a[mi][2] = As[kb + t + 4][mr];
      a[mi][3] = As[kb + t + 4][mr + 8];
    }
    uint32 b[4][2];
#pragma unroll
    for (int ni = 0; ni < 4; ni++) {
      int nc = wn + ni * 8 + g;
      b[ni][0] = Bs[kb + t][nc];
      b[ni][1] = Bs[kb + t + 4][nc];
    }
#pragma unroll
    for (int mi = 0; mi < 2; mi++)
#pragma unroll
      for (int ni = 0; ni < 4; ni++) mma_tf32(c[mi][ni], a[mi], b[ni]);
  }
}

// ===================== 0) repack ConvTranspose weights ======================
__global__ void k_repack_upw(const float* __restrict__ upw, float* __restrict__ dst) {
  int idx = blockIdx.x * 256 + threadIdx.x;   // 1048576
  int t  = idx & 3;
  int ci = (idx >> 2) & 255;
  int co = (idx >> 10) & 255;
  int pc = idx >> 18;
  int py = pc >> 1, px = pc & 1;
  int ky = ((py + 1) & 1) + ((t >> 1) << 1);
  int kx = ((px + 1) & 1) + ((t & 1) << 1);
  dst[idx] = upw[((ci * 256 + co) * 4 + ky) * 4 + kx];
}

// ===================== 1) conv 4x4 stride2 pad1 (fp32, topk-critical) =======
__global__ void __launch_bounds__(256) k_conv_down(const float* __restrict__ x,
    const float* __restrict__ w, const float* __restrict__ bias,
    float* __restrict__ out) {
  __shared__ float As[16][132];
  __shared__ float Bs[16][68];
  float acc[8][4] = {};
  int tid = threadIdx.x, tx = tid & 15, ty = tid >> 4;
  int m0 = blockIdx.y * 128, n0 = blockIdx.x * 64;
  int lkk = tid >> 4, lnn = (tid & 15) * 4;
  for (int k0 = 0; k0 < 4096; k0 += 16) {
    ldA_rowmajor(As, w, 4096, m0, k0, tid);
    {
      int k = k0 + lkk;
      int ci = k >> 4, ky = (k >> 2) & 3, kx = k & 3;
#pragma unroll
      for (int j = 0; j < 4; j++) {
        int n = n0 + lnn + j;
        int b = n >> 10, rem = n & 1023;
        int oy = rem >> 5, ox = rem & 31;
        int iy = 2 * oy + ky - 1, ix = 2 * ox + kx - 1;
        float vv = 0.f;
        if ((unsigned)iy < 64u && (unsigned)ix < 64u)
          vv = x[(((b << 8) + ci) << 12) + (iy << 6) + ix];
        Bs[lkk][lnn + j] = vv;
      }
    }
    __syncthreads();
    fma_tile(As, Bs, acc, tx, ty);
    __syncthreads();
  }
  int n = n0 + tx * 4;
  int b = n >> 10, rem = n & 1023;
#pragma unroll
  for (int i = 0; i < 8; i++) {
    int m = m0 + ty * 8 + i;
    float bi = bias[m];
    float4 o = make_float4(acc[i][0] + bi, acc[i][1] + bi,
                           acc[i][2] + bi, acc[i][3] + bi);
    *(float4*)&out[(((b << 8) + m) << 10) + rem] = o;
  }
}

// ===================== 2) image -> token transpose (coarse) =================
__global__ void k_tokc(const float* __restrict__ xd, float* __restrict__ tok) {
  __shared__ float s[64][65];
  int bh = blockIdx.x, nch = blockIdx.y;   // 32 x 16
  int b = bh >> 2, h = bh & 3;
  int tid = threadIdx.x;
  int n0 = nch * 64;
#pragma unroll
  for (int i = 0; i < 16; i++) {
    int lin = i * 256 + tid;
    int d = lin >> 6, nn = lin & 63;
    s[d][nn] = xd[(((b << 8) + (h << 6) + d) << 10) + n0 + nn];
  }
  __syncthreads();
#pragma unroll
  for (int i = 0; i < 16; i++) {
    int lin = i * 256 + tid;
    int nn = lin >> 6, d = lin & 63;
    tok[((size_t)bh << 16) + ((size_t)(n0 + nn) << 6) + d] = s[d][nn];
  }
}

// ===================== 3) QKV GEMM: [1024,64] @ [64,192] + bias =============
__global__ void __launch_bounds__(256) k_qkv(const float* __restrict__ tok,
    const float* __restrict__ wqkv, const float* __restrict__ bqkv,
    float* __restrict__ q, float* __restrict__ kmat, float* __restrict__ v) {
  __shared__ float As[16][132];
  __shared__ float Bs[16][68];
  float acc[8][4] = {};
  int tid = threadIdx.x, tx = tid & 15, ty = tid >> 4;
  int bh = blockIdx.z;
  int m0 = blockIdx.y * 128, n0 = blockIdx.x * 64;
  const float* A = tok + ((size_t)bh << 16);
  for (int k0 = 0; k0 < 64; k0 += 16) {
    ldA_rowmajor(As, A, 64, m0, k0, tid);
    ldB_rowmajor(Bs, wqkv, 192, k0, n0, tid);
    __syncthreads();
    fma_tile(As, Bs, acc, tx, ty);
    __syncthreads();
  }
  int sec = n0 >> 6;                               // 0:q 1:k 2:v
  float* dst = (sec == 0) ? q : ((sec == 1) ? kmat : v);
  float mul = (sec == 0) ? 0.125f : 1.0f;          // HD^-0.5 folded into q
  int d0 = tx * 4;
#pragma unroll
  for (int i = 0; i < 8; i++) {
    int m = m0 + ty * 8 + i;
    float4 o;
    o.x = (acc[i][0] + bqkv[n0 + d0 + 0]) * mul;
    o.y = (acc[i][1] + bqkv[n0 + d0 + 1]) * mul;
    o.z = (acc[i][2] + bqkv[n0 + d0 + 2]) * mul;
    o.w = (acc[i][3] + bqkv[n0 + d0 + 3]) * mul;
    *(float4*)&dst[((size_t)bh << 16) + ((size_t)m << 6) + d0] = o;
  }
}

// ===================== 4a) coarse S = q @ k^T (fp32, topk-critical) =========
__global__ void __launch_bounds__(256) k_qkT(const float* __restrict__ q,
    const float* __restrict__ kmat, float* __restrict__ attn) {
  __shared__ float As[16][132];
  __shared__ float Bs[16][68];
  float acc[8][4] = {};
  int tid = threadIdx.x, tx = tid & 15, ty = tid >> 4;
  int bh = blockIdx.z, m0 = blockIdx.y * 128, n0 = blockIdx.x * 64;
  const float* A  = q    + ((size_t)bh << 16);
  const float* Bm = kmat + ((size_t)bh << 16);
  for (int k0 = 0; k0 < 64; k0 += 16) {
    ldA_rowmajor(As, A, 64, m0, k0, tid);
    ldB_transposed(Bs, Bm, 64, k0, n0, tid);
    __syncthreads();
    fma_tile(As, Bs, acc, tx, ty);
    __syncthreads();
  }
  float* out = attn + ((size_t)bh << 20);
#pragma unroll
  for (int i = 0; i < 8; i++) {
    int m = m0 + ty * 8 + i;
    float4 o = make_float4(acc[i][0], acc[i][1], acc[i][2], acc[i][3]);
    *(float4*)&out[((size_t)m << 10) + n0 + tx * 4] = o;
  }
}

// ===================== 4b) fine S = q @ k^T (tf32 tensor core) ==============
__global__ void __launch_bounds__(256) k_qkT_t(const float* __restrict__ q,
    const float* __restrict__ kmat, float* __restrict__ attn) {
  __shared__ uint32 As[16][132];
  __shared__ uint32 Bs[16][132];
  float c[4][4][4] = {};
  int tid = threadIdx.x, lane = tid & 31, wid = tid >> 5;
  int wm = (wid & 1) * 64, wn = (wid >> 1) * 32;
  int bh = blockIdx.z, m0 = blockIdx.y * 128, n0 = blockIdx.x * 128;
  const float* A  = q    + ((size_t)bh << 16);
  const float* Bm = kmat + ((size_t)bh << 16);
  for (int k0 = 0; k0 < 64; k0 += 16) {
    ldA_tf32(As, A, 64, m0, k0, tid);
    ldB_t_tf32(Bs, Bm, 64, k0, n0, tid);
    __syncthreads();
    mma_tile_tf32(As, Bs, c, lane, wm, wn);
    __syncthreads();
  }
  int g = lane >> 2, t2 = (lane & 3) * 2;
  float* out = attn + ((size_t)bh << 20);
#pragma unroll
  for (int mi = 0; mi < 4; mi++) {
    int m = m0 + wm + mi * 16 + g;
#pragma unroll
    for (int ni = 0; ni < 4; ni++) {
      int col = n0 + wn + ni * 8 + t2;
      *(float2*)&out[((size_t)m << 10) + col] =
          make_float2(c[mi][ni][0], c[mi][ni][1]);
      *(float2*)&out[((size_t)(m + 8) << 10) + col] =
          make_float2(c[mi][ni][2], c[mi][ni][3]);
    }
  }
}

// ===================== 5) row softmax in place ==============================
__global__ void __launch_bounds__(256) k_softmax(float* __restrict__ attn) {
  int row = blockIdx.x, bh = blockIdx.y;
  float* p = attn + ((size_t)bh << 20) + ((size_t)row << 10);
  int tid = threadIdx.x;
  float4 v = *(float4*)&p[tid * 4];
  __shared__ float red[256];
  float mx = fmaxf(fmaxf(v.x, v.y), fmaxf(v.z, v.w));
  red[tid] = mx;
  __syncthreads();
  for (int s = 128; s > 0; s >>= 1) {
    if (tid < s) red[tid] = fmaxf(red[tid], red[tid + s]);
    __syncthreads();
  }
  mx = red[0];
  __syncthreads();
  v.x = __expf(v.x - mx); v.y = __expf(v.y - mx);
  v.z = __expf(v.z - mx); v.w = __expf(v.w - mx);
  red[tid] = (v.x + v.y) + (v.z + v.w);
  __syncthreads();
  for (int s = 128; s > 0; s >>= 1) {
    if (tid < s) red[tid] += red[tid + s];
    __syncthreads();
  }
  float inv = 1.0f / red[0];
  v.x *= inv; v.y *= inv; v.z *= inv; v.w *= inv;
  *(float4*)&p[tid * 4] = v;
}

// ===================== 6) column sums (deterministic 2-phase) ===============
__global__ void k_colsum_part(const float* __restrict__ attn, float* __restrict__ part) {
  int bh = blockIdx.x, ny = blockIdx.y, m = threadIdx.x;  // 32 x 8, 1024 thr
  const float* p = attn + ((size_t)bh << 20) + ((size_t)(ny * 128) << 10) + m;
  float a0 = 0, a1 = 0, a2 = 0, a3 = 0;
  for (int n = 0; n < 128; n += 4) {
    a0 += p[(size_t)(n + 0) << 10];
    a1 += p[(size_t)(n + 1) << 10];
    a2 += p[(size_t)(n + 2) << 10];
    a3 += p[(size_t)(n + 3) << 10];
  }
  part[(bh * 8 + ny) * 1024 + m] = (a0 + a1) + (a2 + a3);
}
__global__ void k_colsum_red(const float* __restrict__ part, float* __restrict__ score) {
  int bh = blockIdx.x, m = threadIdx.x;
  float a = 0;
#pragma unroll
  for (int i = 0; i < 8; i++) a += part[(bh * 8 + i) * 1024 + m];
  score[bh * 1024 + m] = a;
}

// ===================== 7) top-256 by rank (matches lax.top_k order) =========
__global__ void k_topk(const float* __restrict__ score, int* __restrict__ topk) {
  int bh = blockIdx.x;
  __shared__ float s[1024];
  int tid = threadIdx.x;   // 1024
  s[tid] = score[bh * 1024 + tid];
  __syncthreads();
  float mine = s[tid];
  int rank = 0;
  for (int j = 0; j < 1024; j++) {
    float o = s[j];
    rank += (o > mine) || (o == mine && j < tid);
  }
  if (rank < 256) topk[bh * 256 + rank] = tid;
}

// ===================== 8) out = attn @ v (tf32 tensor core) =================
// mode 0: write [bh][m][64] row-major (fine). mode 1: image layout aout.
__global__ void __launch_bounds__(256) k_av_t(const float* __restrict__ attn,
    const float* __restrict__ v, float* __restrict__ out, int mode) {
  __shared__ uint32 As[16][132];
  __shared__ uint32 Bs[16][68];
  float c[2][4][4] = {};
  int tid = threadIdx.x, lane = tid & 31, wid = tid >> 5;
  int wm = (wid & 3) * 32, wn = (wid >> 2) * 32;
  int bh = blockIdx.z, m0 = blockIdx.y * 128;
  const float* A  = attn + ((size_t)bh << 20);
  const float* Bm = v    + ((size_t)bh << 16);
  int bkk = tid >> 4, bnn = (tid & 15) * 4;
  for (int k0 = 0; k0 < 1024; k0 += 16) {
    ldA_tf32(As, A, 1024, m0, k0, tid);
    {
      float4 x = *(const float4*)(Bm + (size_t)(k0 + bkk) * 64 + bnn);
      Bs[bkk][bnn + 0] = tf32cvt(x.x); Bs[bkk][bnn + 1] = tf32cvt(x.y);
      Bs[bkk][bnn + 2] = tf32cvt(x.z); Bs[bkk][bnn + 3] = tf32cvt(x.w);
    }
    __syncthreads();
    mma_tile_tf32_32(As, Bs, c, lane, wm, wn);
    __syncthreads();
  }
  int g = lane >> 2, t2 = (lane & 3) * 2;
  if (mode == 0) {
    float* dst0 = out + ((size_t)bh << 16);
#pragma unroll
    for (int mi = 0; mi < 2; mi++) {
      int m = m0 + wm + mi * 16 + g;
#pragma unroll
      for (int ni = 0; ni < 4; ni++) {
        int col = wn + ni * 8 + t2;
        *(float2*)&dst0[((size_t)m << 6) + col] =
            make_float2(c[mi][ni][0], c[mi][ni][1]);
        *(float2*)&dst0[((size_t)(m + 8) << 6) + col] =
            make_float2(c[mi][ni][2], c[mi][ni][3]);
      }
    }
  } else {
    int b = bh >> 2, h = bh & 3;
#pragma unroll
    for (int mi = 0; mi < 2; mi++) {
      int m = m0 + wm + mi * 16 + g;
#pragma unroll
      for (int ni = 0; ni < 4; ni++) {
        int d = wn + ni * 8 + t2;
        float* base0 = &out[(((b << 8) + (h << 6) + d) << 10)];
        float* base1 = base0 + (1 << 10);
        base0[m]     = c[mi][ni][0];
        base1[m]     = c[mi][ni][1];
        base0[m + 8] = c[mi][ni][2];
        base1[m + 8] = c[mi][ni][3];
      }
    }
  }
}

// ===================== 9) ConvTranspose 4x4 s2 p1 — tf32 tensor core ========
// M=256 co, N=8192 (b, 32x32 half-res), K=1024 (ci*4 + tap). BM=128, BN=128.
__global__ void __launch_bounds__(256) k_conv_up_t(const float* __restrict__ ain,
    const float* __restrict__ wre, const float* __restrict__ bias,
    float* __restrict__ out) {
  __shared__ uint32 As[16][132];
  __shared__ uint32 Bs[16][132];
  float c[4][4][4] = {};
  int tid = threadIdx.x, lane = tid & 31, wid = tid >> 5;
  int wm = (wid & 1) * 64, wn = (wid >> 1) * 32;
  int m0 = blockIdx.y * 128, n0 = blockIdx.x * 128;
  int pc = blockIdx.z;
  int py = pc >> 1, px = pc & 1;
  const float* A = wre + (size_t)pc * 262144;
  int lkk = tid >> 4, lnn = (tid & 15) * 8;
  int dy0 = (py + 1) >> 1, dx0 = (px + 1) >> 1;
  int bimg = n0 >> 10, rem0 = (n0 & 1023) + lnn;
  const float* ab = ain + ((size_t)bimg << 18);
  for (int k0 = 0; k0 < 1024; k0 += 16) {
    ldA_tf32(As, A, 1024, m0, k0, tid);
    {
      int k = k0 + lkk;
      int ci = k >> 2, t = k & 3;
      int dy = dy0 - (t >> 1), dx = dx0 - (t & 1);
      const float* ac = ab + ((size_t)ci << 10);
#pragma unroll
      for (int j = 0; j < 8; j++) {
        int rem = rem0 + j;
        int iy = (rem >> 5) + dy, ix = (rem & 31) + dx;
        float vv = 0.f;
        if ((unsigned)iy < 32u && (unsigned)ix < 32u) vv = ac[(iy << 5) + ix];
        Bs[lkk][lnn + j] = tf32cvt(vv);
      }
    }
    __syncthreads();
    mma_tile_tf32(As, Bs, c, lane, wm, wn);
    __syncthreads();
  }
  int g = lane >> 2, t2 = (lane & 3) * 2;
#pragma unroll
  for (int mi = 0; mi < 4; mi++) {
    int m = m0 + wm + mi * 16 + g;
    float bi0 = bias[m], bi1 = bias[m + 8];
    float* base0 = &out[(((bimg << 8) + m) << 12)];
    float* base1 = base0 + (8 << 12);
#pragma unroll
    for (int ni = 0; ni < 4; ni++) {
      int ln = wn + ni * 8 + t2;
      int rem = (n0 & 1023) + ln;
      int oy2 = rem >> 5, ox2 = rem & 31;
      int off = ((2 * oy2 + py) << 6) + 2 * ox2 + px;
      base0[off]     = c[mi][ni][0] + bi0;
      base0[off + 2] = c[mi][ni][1] + bi0;
      base1[off]     = c[mi][ni][2] + bi1;
      base1[off + 2] = c[mi][ni][3] + bi1;
    }
  }
}

// ===================== 10) gather fine tokens ===============================
__global__ void k_gather(const float* __restrict__ coarse, const int* __restrict__ topk,
                         float* __restrict__ tok) {
  int bh = blockIdx.x, chunk = blockIdx.y;   // 32 x 16
  int tid = threadIdx.x;
  int d = tid & 63;
  int b = bh >> 2, h = bh & 3;
#pragma unroll
  for (int i = 0; i < 16; i++) {
    int j = chunk * 64 + (tid >> 6) + i * 4;  // token 0..1023
    int p = j >> 2, l = j & 3;
    int qq = topk[bh * 256 + p];
    int py = ((qq >> 5) << 1) + (l >> 1);
    int px = ((qq & 31) << 1) + (l & 1);
    tok[((size_t)bh << 16) + ((size_t)j << 6) + d] =
        coarse[(((b << 8) + (h << 6) + d) << 12) + (py << 6) + px];
  }
}

// ===================== 11) scatter-add fine outputs into coarse =============
__global__ void k_scatter(const float* __restrict__ outf, const int* __restrict__ topk,
                          float* __restrict__ coarse) {
  int bh = blockIdx.x, chunk = blockIdx.y;
  int tid = threadIdx.x;
  int d = tid & 63;
  int b = bh >> 2, h = bh & 3;
#pragma unroll
  for (int i = 0; i < 16; i++) {
    int j = chunk * 64 + (tid >> 6) + i * 4;
    int p = j >> 2, l = j & 3;
    int qq = topk[bh * 256 + p];
    int py = ((qq >> 5) << 1) + (l >> 1);
    int px = ((qq & 31) << 1) + (l & 1);
    coarse[(((b << 8) + (h << 6) + d) << 12) + (py << 6) + px] +=
        outf[((size_t)bh << 16) + ((size_t)j << 6) + d];
  }
}

// ===================== 12) depthwise 3x3 + BN1 + ReLU6 ======================
__global__ void k_dw(const float* __restrict__ y, const float* __restrict__ w,
    const float* __restrict__ g, const float* __restrict__ bb,
    const float* __restrict__ mm, const float* __restrict__ vv,
    float* __restrict__ out) {
  int idx = blockIdx.x * 256 + threadIdx.x;   // 8*256*4096
  int x = idx & 63, yy = (idx >> 6) & 63, c = (idx >> 12) & 255, b = idx >> 20;
  const float* base = y + ((size_t)((b << 8) + c) << 12);
  float acc = 0.f;
#pragma unroll
  for (int ky = 0; ky < 3; ky++) {
    int iy = yy + ky - 1;
    if ((unsigned)iy >= 64u) continue;
#pragma unroll
    for (int kx = 0; kx < 3; kx++) {
      int ix = x + kx - 1;
      if ((unsigned)ix >= 64u) continue;
      acc += w[c * 9 + ky * 3 + kx] * base[(iy << 6) + ix];
    }
  }
  float inv = g[c] * rsqrtf(vv[c] + 1e-5f);
  float val = acc * inv + (bb[c] - mm[c] * inv);
  out[idx] = fminf(fmaxf(val, 0.f), 6.f);
}

// ===================== 13) pointwise 1x1 + BN2 + ReLU6 — tf32 tensor core ===
// M=256 co, N=32768 (b, 64x64), K=256. BM=128, BN=128.
__global__ void __launch_bounds__(256) k_pw_t(const float* __restrict__ y1,
    const float* __restrict__ w, const float* __restrict__ bn_g,
    const float* __restrict__ bn_b, const float* __restrict__ bn_m,
    const float* __restrict__ bn_v, float* __restrict__ out) {
  __shared__ uint32 As[16][132];
  __shared__ uint32 Bs[16][132];
  float c[4][4][4] = {};
  int tid = threadIdx.x, lane = tid & 31, wid = tid >> 5;
  int wm = (wid & 1) * 64, wn = (wid >> 1) * 32;
  int m0 = blockIdx.y * 128, n0 = blockIdx.x * 128;
  int lkk = tid >> 4, lnn = (tid & 15) * 8;
  int bB = n0 >> 12, remB = (n0 & 4095) + lnn;
  const float* yb = y1 + ((size_t)bB << 20);
  for (int k0 = 0; k0 < 256; k0 += 16) {
    ldA_tf32(As, w, 256, m0, k0, tid);
    {
      const float* src = yb + ((size_t)(k0 + lkk) << 12) + remB;
      float4 x0 = *(const float4*)(src);
      float4 x1 = *(const float4*)(src + 4);
      Bs[lkk][lnn + 0] = tf32cvt(x0.x); Bs[lkk][lnn + 1] = tf32cvt(x0.y);
      Bs[lkk][lnn + 2] = tf32cvt(x0.z); Bs[lkk][lnn + 3] = tf32cvt(x0.w);
      Bs[lkk][lnn + 4] = tf32cvt(x1.x); Bs[lkk][lnn + 5] = tf32cvt(x1.y);
      Bs[lkk][lnn + 6] = tf32cvt(x1.z); Bs[lkk][lnn + 7] = tf32cvt(x1.w);
    }
    __syncthreads();
    mma_tile_tf32(As, Bs, c, lane, wm, wn);
    __syncthreads();
  }
  int g = lane >> 2, t2 = (lane & 3) * 2;
#pragma unroll
  for (int mi = 0; mi < 4; mi++) {
    int m = m0 + wm + mi * 16 + g;
    float inv0 = bn_g[m] * rsqrtf(bn_v[m] + 1e-5f);
    float add0 = bn_b[m] - bn_m[m] * inv0;
    float inv1 = bn_g[m + 8] * rsqrtf(bn_v[m + 8] + 1e-5f);
    float add1 = bn_b[m + 8] - bn_m[m + 8] * inv1;
    float* base0 = &out[(((size_t)(bB << 8) + m) << 12)];
    float* base1 = base0 + (8 << 12);
#pragma unroll
    for (int ni = 0; ni < 4; ni++) {
      int rem = (n0 & 4095) + wn + ni * 8 + t2;
      float2 o0, o1;
      o0.x = fminf(fmaxf(c[mi][ni][0] * inv0 + add0, 0.f), 6.f);
      o0.y = fminf(fmaxf(c[mi][ni][1] * inv0 + add0, 0.f), 6.f);
      o1.x = fminf(fmaxf(c[mi][ni][2] * inv1 + add1, 0.f), 6.f);
      o1.y = fminf(fmaxf(c[mi][ni][3] * inv1 + add1, 0.f), 6.f);
      *(float2*)&base0[rem] = o0;
      *(float2*)&base1[rem] = o1;
    }
  }
}

// ===================== host launcher ========================================
static float* symf(const void* s) {
  void* p = nullptr;
  cudaGetSymbolAddress(&p, s);
  return (float*)p;
}

extern "C" void kernel_launch(void* const* d_in, const int* in_sizes, int n_in,
                              void* d_out, int out_size) {
  const float* x      = (const float*)d_in[0];
  const float* down_w = (const float*)d_in[1];
  const float* down_b = (const float*)d_in[2];
  const float* up_w   = (const float*)d_in[3];
  const float* up_b   = (const float*)d_in[4];
  const float* wqkv_c = (const float*)d_in[5];
  const float* bqkv_c = (const float*)d_in[6];
  const float* wqkv_f = (const float*)d_in[7];
  const float* bqkv_f = (const float*)d_in[8];
  const float* dw_w   = (const float*)d_in[9];
  const float* bn1_g  = (const float*)d_in[10];
  const float* bn1_b  = (const float*)d_in[11];
  const float* bn1_m  = (const float*)d_in[12];
  const float* bn1_v  = (const float*)d_in[13];
  const float* pw_w   = (const float*)d_in[14];
  const float* bn2_g  = (const float*)d_in[15];
  const float* bn2_b  = (const float*)d_in[16];
  const float* bn2_m  = (const float*)d_in[17];
  const float* bn2_v  = (const float*)d_in[18];
  float* out = (float*)d_out;

  float* xd     = symf(g_xd);
  float* tok    = symf(g_tok);
  float* q      = symf(g_q);
  float* kk     = symf(g_kk);
  float* v      = symf(g_v);
  float* attn   = symf(g_attn);
  float* part   = symf(g_part);
  float* score  = symf(g_score);
  int*   topk   = (int*)symf(g_topk);
  float* aout   = symf(g_aout);
  float* coarse = symf(g_coarse);
  float* outf   = symf(g_outf);
  float* y1     = symf(g_y1);
  float* upw    = symf(g_upw);

  // ---- coarse branch ----
  k_repack_upw<<<4096, 256>>>(up_w, upw);
  k_conv_down<<<dim3(128, 2), 256>>>(x, down_w, down_b, xd);
  k_tokc<<<dim3(32, 16), 256>>>(xd, tok);
  k_qkv<<<dim3(3, 8, 32), 256>>>(tok, wqkv_c, bqkv_c, q, kk, v);
  k_qkT<<<dim3(16, 8, 32), 256>>>(q, kk, attn);
  k_softmax<<<dim3(1024, 32), 256>>>(attn);
  k_colsum_part<<<dim3(32, 8), 1024>>>(attn, part);
  k_colsum_red<<<32, 1024>>>(part, score);
  k_topk<<<32, 1024>>>(score, topk);
  k_av_t<<<dim3(1, 8, 32), 256>>>(attn, v, aout, 1);
  k_conv_up_t<<<dim3(64, 2, 4), 256>>>(aout, upw, up_b, coarse);

  // ---- fine branch ----
  k_gather<<<dim3(32, 16), 256>>>(coarse, topk, tok);
  k_qkv<<<dim3(3, 8, 32), 256>>>(tok, wqkv_f, bqkv_f, q, kk, v);
  k_qkT_t<<<dim3(8, 8, 32), 256>>>(q, kk, attn);
  k_softmax<<<dim3(1024, 32), 256>>>(attn);
  k_av_t<<<dim3(1, 8, 32), 256>>>(attn, v, outf, 0);
  k_scatter<<<dim3(32, 16), 256>>>(outf, topk, coarse);

  // ---- DWConv block ----
  k_dw<<<32768, 256>>>(coarse, dw_w, bn1_g, bn1_b, bn1_m, bn1_v, y1);
  k_pw_t<<<dim3(256, 2), 256>>>(y1, pw_w, bn2_g, bn2_b, bn2_m, bn2_v, out);
}

// round 11
// speedup vs baseline: 1.3378x; 1.0016x over previous
#include <cuda_runtime.h>
#include <cstddef>

typedef unsigned int uint32;

// ===================== problem constants =====================
// B=8, C=256, H=W=64, HD=64, NH=4 heads, BH=B*NH=32, N=1024 coarse tokens,
// KF=256 selected patches, PS=2.

// ===================== device scratch (no allocations allowed) =============
__device__ float g_xd[2097152];      // [8,256,32,32] downsampled
__device__ float g_tok[2097152];     // [32,1024,64] tokens (coarse, then fine)
__device__ float g_q[2097152];       // [32,1024,64] (q pre-scaled by 0.125)
__device__ float g_kk[2097152];      // [32,1024,64]
__device__ float g_v[2097152];       // [32,1024,64]
__device__ float g_attn[33554432];   // [32,1024,1024]
__device__ float g_part[262144];     // [32,8,1024] colsum partials
__device__ float g_score[32768];     // [32,1024]
__device__ int   g_topk[8192];       // [32,256]
__device__ float g_aout[2097152];    // [8,256,32,32] coarse attn out (image layout)
__device__ float g_coarse[8388608];  // [8,256,64,64]
__device__ float g_outf[2097152];    // [32,1024,64] fine attn out
__device__ float g_y1[8388608];      // [8,256,64,64] after dw+bn1+relu6
__device__ float g_upw[1048576];     // [4 parity][256 co][256 ci *4 taps]

// ===================== fp32 SIMT GEMM microkernel ===========================
// Tile: BM=128, BN=64, BK=16. 256 threads. Each thread: 8x4 outputs.

__device__ __forceinline__ void ldA_rowmajor(float (&As)[16][132],
    const float* __restrict__ A, int lda, int m0, int k0, int tid) {
  int m  = tid >> 1;             // 0..127
  int kq = (tid & 1) * 8;        // 0 or 8
  const float* src = A + (size_t)(m0 + m) * lda + k0 + kq;
  float4 x0 = *(const float4*)(src);
  float4 x1 = *(const float4*)(src + 4);
  As[kq + 0][m] = x0.x; As[kq + 1][m] = x0.y;
  As[kq + 2][m] = x0.z; As[kq + 3][m] = x0.w;
  As[kq + 4][m] = x1.x; As[kq + 5][m] = x1.y;
  As[kq + 6][m] = x1.z; As[kq + 7][m] = x1.w;
}

__device__ __forceinline__ void ldB_rowmajor(float (&Bs)[16][68],
    const float* __restrict__ Bm, int ldb, int k0, int n0, int tid) {
  int kk = tid >> 4;             // 0..15
  int nn = (tid & 15) * 4;       // 0..60
  float4 x = *(const float4*)(Bm + (size_t)(k0 + kk) * ldb + n0 + nn);
  *(float4*)&Bs[kk][nn] = x;
}

__device__ __forceinline__ void ldB_transposed(float (&Bs)[16][68],
    const float* __restrict__ Bm, int ldb, int k0, int n0, int tid) {
  int n  = tid >> 2;             // 0..63
  int kq = (tid & 3) * 4;        // 0..12
  float4 x = *(const float4*)(Bm + (size_t)(n0 + n) * ldb + k0 + kq);
  Bs[kq + 0][n] = x.x; Bs[kq + 1][n] = x.y;
  Bs[kq + 2][n] = x.z; Bs[kq + 3][n] = x.w;
}

__device__ __forceinline__ void fma_tile(const float (&As)[16][132],
    const float (&Bs)[16][68], float (&acc)[8][4], int tx, int ty) {
#pragma unroll
  for (int kk = 0; kk < 16; kk++) {
    float4 a0 = *(const float4*)&As[kk][ty * 8];
    float4 a1 = *(const float4*)&As[kk][ty * 8 + 4];
    float4 b4 = *(const float4*)&Bs[kk][tx * 4];
    float av[8] = {a0.x, a0.y, a0.z, a0.w, a1.x, a1.y, a1.z, a1.w};
    float bv[4] = {b4.x, b4.y, b4.z, b4.w};
#pragma unroll
    for (int i = 0; i < 8; i++)
#pragma unroll
      for (int j = 0; j < 4; j++) acc[i][j] += av[i] * bv[j];
  }
}

// ===================== tf32 mma.sync primitives =============================
__device__ __forceinline__ uint32 tf32cvt(float x) {
  uint32 r;
  asm("cvt.rna.tf32.f32 %0, %1;" : "=r"(r) : "f"(x));
  return r;
}
__device__ __forceinline__ void mma_tf32(float (&c)[4], const uint32 (&a)[4],
                                         const uint32 (&b)[2]) {
  asm volatile(
      "mma.sync.aligned.m16n8k8.row.col.f32.tf32.tf32.f32 "
      "{%0,%1,%2,%3}, {%4,%5,%6,%7}, {%8,%9}, {%0,%1,%2,%3};"
      : "+f"(c[0]), "+f"(c[1]), "+f"(c[2]), "+f"(c[3])
      : "r"(a[0]), "r"(a[1]), "r"(a[2]), "r"(a[3]), "r"(b[0]), "r"(b[1]));
}

// tf32 A staging: As[k][m] bits, BM=128, BK=16, row-major fp32 source.
__device__ __forceinline__ void ldA_tf32(uint32 (&As)[16][132],
    const float* __restrict__ A, int lda, int m0, int k0, int tid) {
  int m  = tid >> 1;
  int kq = (tid & 1) * 8;
  const float* src = A + (size_t)(m0 + m) * lda + k0 + kq;
  float4 x0 = *(const float4*)(src);
  float4 x1 = *(const float4*)(src + 4);
  As[kq + 0][m] = tf32cvt(x0.x); As[kq + 1][m] = tf32cvt(x0.y);
  As[kq + 2][m] = tf32cvt(x0.z); As[kq + 3][m] = tf32cvt(x0.w);
  As[kq + 4][m] = tf32cvt(x1.x); As[kq + 5][m] = tf32cvt(x1.y);
  As[kq + 6][m] = tf32cvt(x1.z); As[kq + 7][m] = tf32cvt(x1.w);
}

// tf32 transposed B staging: Bs[k][n] = Bm[n0+n][k0+k], BN=128, BK=16.
__device__ __forceinline__ void ldB_t_tf32(uint32 (&Bs)[16][132],
    const float* __restrict__ Bm, int ldb, int k0, int n0, int tid) {
  int n  = tid >> 1;
  int kq = (tid & 1) * 8;
  const float* src = Bm + (size_t)(n0 + n) * ldb + k0 + kq;
  float4 x0 = *(const float4*)(src);
  float4 x1 = *(const float4*)(src + 4);
  Bs[kq + 0][n] = tf32cvt(x0.x); Bs[kq + 1][n] = tf32cvt(x0.y);
  Bs[kq + 2][n] = tf32cvt(x0.z); Bs[kq + 3][n] = tf32cvt(x0.w);
  Bs[kq + 4][n] = tf32cvt(x1.x); Bs[kq + 5][n] = tf32cvt(x1.y);
  Bs[kq + 6][n] = tf32cvt(x1.z); Bs[kq + 7][n] = tf32cvt(x1.w);
}

// Warp-level 64x32 tf32 tile over block tile 128x128 (8 warps = 2m x 4n).
__device__ __forceinline__ void mma_tile_tf32(const uint32 (&As)[16][132],
    const uint32 (&Bs)[16][132], float (&c)[4][4][4], int lane, int wm, int wn) {
  int g = lane >> 2, t = lane & 3;
#pragma unroll
  for (int ks = 0; ks < 2; ks++) {
    int kb = ks * 8;
    uint32 a[4][4];
#pragma unroll
    for (int mi = 0; mi < 4; mi++) {
      int mr = wm + mi * 16 + g;
      a[mi][0] = As[kb + t][mr];
      a[mi][1] = As[kb + t][mr + 8];
      a[mi][2] = As[kb + t + 4][mr];
      a[mi][3] = As[kb + t + 4][mr + 8];
    }
    uint32 b[4][2];
#pragma unroll
    for (int ni = 0; ni < 4; ni++) {
      int nc = wn + ni * 8 + g;
      b[ni][0] = Bs[kb + t][nc];
      b[ni][1] = Bs[kb + t + 4][nc];
    }
#pragma unroll
    for (int mi = 0; mi < 4; mi++)
#pragma unroll
      for (int ni = 0; ni < 4; ni++) mma_tf32(c[mi][ni], a[mi], b[ni]);
  }
}

// Warp-level 32x32 tf32 tile over block tile 128x64 (8 warps = 4m x 2n).
__device__ __forceinline__ void mma_tile_tf32_32(const uint32 (&As)[16][132],
    const uint32 (&Bs)[16][68], float (&c)[2][4][4], int lane, int wm, int wn) {
  int g = lane >> 2, t = lane & 3;
#pragma unroll
  for (int ks = 0; ks < 2; ks++) {
    int kb = ks * 8;
    uint32 a[2][4];
#pragma unroll
    for (int mi = 0; mi < 2; mi++) {
      int mr = wm + mi * 16 + g;
      a[mi][0] = As[kb + t][mr];
      a[mi][1] = As[kb + t][mr + 8];
      a[mi][2] = As[kb + t + 4][mr];
      a[mi][3] = As[kb + t + 4][mr + 8];
    }
    uint32 b[4][2];
#pragma unroll
    for (int ni = 0; ni < 4; ni++) {
      int nc = wn + ni * 8 + g;
      b[ni][0] = Bs[kb + t][nc];
      b[ni][1] = Bs[kb + t + 4][nc];
    }
#pragma unroll
    for (int mi = 0; mi < 2; mi++)
#pragma unroll
      for (int ni = 0; ni < 4; ni++) mma_tf32(c[mi][ni], a[mi], b[ni]);
  }
}

// ===================== 0) repack ConvTranspose weights ======================
__global__ void k_repack_upw(const float* __restrict__ upw, float* __restrict__ dst) {
  int idx = blockIdx.x * 256 + threadIdx.x;   // 1048576
  int t  = idx & 3;
  int ci = (idx >> 2) & 255;
  int co = (idx >> 10) & 255;
  int pc = idx >> 18;
  int py = pc >> 1, px = pc & 1;
  int ky = ((py + 1) & 1) + ((t >> 1) << 1);
  int kx = ((px + 1) & 1) + ((t & 1) << 1);
  dst[idx] = upw[((ci * 256 + co) * 4 + ky) * 4 + kx];
}

// ===================== 1) conv 4x4 stride2 pad1 (fp32, topk-critical) =======
__global__ void __launch_bounds__(256) k_conv_down(const float* __restrict__ x,
    const float* __restrict__ w, const float* __restrict__ bias,
    float* __restrict__ out) {
  __shared__ float As[16][132];
  __shared__ float Bs[16][68];
  float acc[8][4] = {};
  int tid = threadIdx.x, tx = tid & 15, ty = tid >> 4;
  int m0 = blockIdx.y * 128, n0 = blockIdx.x * 64;
  int lkk = tid >> 4, lnn = (tid & 15) * 4;
  for (int k0 = 0; k0 < 4096; k0 += 16) {
    ldA_rowmajor(As, w, 4096, m0, k0, tid);
    {
      int k = k0 + lkk;
      int ci = k >> 4, ky = (k >> 2) & 3, kx = k & 3;
#pragma unroll
      for (int j = 0; j < 4; j++) {
        int n = n0 + lnn + j;
        int b = n >> 10, rem = n & 1023;
        int oy = rem >> 5, ox = rem & 31;
        int iy = 2 * oy + ky - 1, ix = 2 * ox + kx - 1;
        float vv = 0.f;
        if ((unsigned)iy < 64u && (unsigned)ix < 64u)
          vv = x[(((b << 8) + ci) << 12) + (iy << 6) + ix];
        Bs[lkk][lnn + j] = vv;
      }
    }
    __syncthreads();
    fma_tile(As, Bs, acc, tx, ty);
    __syncthreads();
  }
  int n = n0 + tx * 4;
  int b = n >> 10, rem = n & 1023;
#pragma unroll
  for (int i = 0; i < 8; i++) {
    int m = m0 + ty * 8 + i;
    float bi = bias[m];
    float4 o = make_float4(acc[i][0] + bi, acc[i][1] + bi,
                           acc[i][2] + bi, acc[i][3] + bi);
    *(float4*)&out[(((b << 8) + m) << 10) + rem] = o;
  }
}

// ===================== 2) image -> token transpose (coarse) =================
__global__ void k_tokc(const float* __restrict__ xd, float* __restrict__ tok) {
  __shared__ float s[64][65];
  int bh = blockIdx.x, nch = blockIdx.y;   // 32 x 16
  int b = bh >> 2, h = bh & 3;
  int tid = threadIdx.x;
  int n0 = nch * 64;
#pragma unroll
  for (int i = 0; i < 16; i++) {
    int lin = i * 256 + tid;
    int d = lin >> 6, nn = lin & 63;
    s[d][nn] = xd[(((b << 8) + (h << 6) + d) << 10) + n0 + nn];
  }
  __syncthreads();
#pragma unroll
  for (int i = 0; i < 16; i++) {
    int lin = i * 256 + tid;
    int nn = lin >> 6, d = lin & 63;
    tok[((size_t)bh << 16) + ((size_t)(n0 + nn) << 6) + d] = s[d][nn];
  }
}

// ===================== 3) QKV GEMM: [1024,64] @ [64,192] + bias =============
__global__ void __launch_bounds__(256) k_qkv(const float* __restrict__ tok,
    const float* __restrict__ wqkv, const float* __restrict__ bqkv,
    float* __restrict__ q, float* __restrict__ kmat, float* __restrict__ v) {
  __shared__ float As[16][132];
  __shared__ float Bs[16][68];
  float acc[8][4] = {};
  int tid = threadIdx.x, tx = tid & 15, ty = tid >> 4;
  int bh = blockIdx.z;
  int m0 = blockIdx.y * 128, n0 = blockIdx.x * 64;
  const float* A = tok + ((size_t)bh << 16);
  for (int k0 = 0; k0 < 64; k0 += 16) {
    ldA_rowmajor(As, A, 64, m0, k0, tid);
    ldB_rowmajor(Bs, wqkv, 192, k0, n0, tid);
    __syncthreads();
    fma_tile(As, Bs, acc, tx, ty);
    __syncthreads();
  }
  int sec = n0 >> 6;                               // 0:q 1:k 2:v
  float* dst = (sec == 0) ? q : ((sec == 1) ? kmat : v);
  float mul = (sec == 0) ? 0.125f : 1.0f;          // HD^-0.5 folded into q
  int d0 = tx * 4;
#pragma unroll
  for (int i = 0; i < 8; i++) {
    int m = m0 + ty * 8 + i;
    float4 o;
    o.x = (acc[i][0] + bqkv[n0 + d0 + 0]) * mul;
    o.y = (acc[i][1] + bqkv[n0 + d0 + 1]) * mul;
    o.z = (acc[i][2] + bqkv[n0 + d0 + 2]) * mul;
    o.w = (acc[i][3] + bqkv[n0 + d0 + 3]) * mul;
    *(float4*)&dst[((size_t)bh << 16) + ((size_t)m << 6) + d0] = o;
  }
}

// ===================== 4a) coarse S = q @ k^T (fp32, topk-critical) =========
__global__ void __launch_bounds__(256) k_qkT(const float* __restrict__ q,
    const float* __restrict__ kmat, float* __restrict__ attn) {
  __shared__ float As[16][132];
  __shared__ float Bs[16][68];
  float acc[8][4] = {};
  int tid = threadIdx.x, tx = tid & 15, ty = tid >> 4;
  int bh = blockIdx.z, m0 = blockIdx.y * 128, n0 = blockIdx.x * 64;
  const float* A  = q    + ((size_t)bh << 16);
  const float* Bm = kmat + ((size_t)bh << 16);
  for (int k0 = 0; k0 < 64; k0 += 16) {
    ldA_rowmajor(As, A, 64, m0, k0, tid);
    ldB_transposed(Bs, Bm, 64, k0, n0, tid);
    __syncthreads();
    fma_tile(As, Bs, acc, tx, ty);
    __syncthreads();
  }
  float* out = attn + ((size_t)bh << 20);
#pragma unroll
  for (int i = 0; i < 8; i++) {
    int m = m0 + ty * 8 + i;
    float4 o = make_float4(acc[i][0], acc[i][1], acc[i][2], acc[i][3]);
    *(float4*)&out[((size_t)m << 10) + n0 + tx * 4] = o;
  }
}

// ===================== 4b) fine S = q @ k^T (tf32 tensor core) ==============
__global__ void __launch_bounds__(256) k_qkT_t(const float* __restrict__ q,
    const float* __restrict__ kmat, float* __restrict__ attn) {
  __shared__ uint32 As[16][132];
  __shared__ uint32 Bs[16][132];
  float c[4][4][4] = {};
  int tid = threadIdx.x, lane = tid & 31, wid = tid >> 5;
  int wm = (wid & 1) * 64, wn = (wid >> 1) * 32;
  int bh = blockIdx.z, m0 = blockIdx.y * 128, n0 = blockIdx.x * 128;
  const float* A  = q    + ((size_t)bh << 16);
  const float* Bm = kmat + ((size_t)bh << 16);
  for (int k0 = 0; k0 < 64; k0 += 16) {
    ldA_tf32(As, A, 64, m0, k0, tid);
    ldB_t_tf32(Bs, Bm, 64, k0, n0, tid);
    __syncthreads();
    mma_tile_tf32(As, Bs, c, lane, wm, wn);
    __syncthreads();
  }
  int g = lane >> 2, t2 = (lane & 3) * 2;
  float* out = attn + ((size_t)bh << 20);
#pragma unroll
  for (int mi = 0; mi < 4; mi++) {
    int m = m0 + wm + mi * 16 + g;
#pragma unroll
    for (int ni = 0; ni < 4; ni++) {
      int col = n0 + wn + ni * 8 + t2;
      *(float2*)&out[((size_t)m << 10) + col] =
          make_float2(c[mi][ni][0], c[mi][ni][1]);
      *(float2*)&out[((size_t)(m + 8) << 10) + col] =
          make_float2(c[mi][ni][2], c[mi][ni][3]);
    }
  }
}

// ===================== 5) row softmax in place ==============================
__global__ void __launch_bounds__(256) k_softmax(float* __restrict__ attn) {
  int row = blockIdx.x, bh = blockIdx.y;
  float* p = attn + ((size_t)bh << 20) + ((size_t)row << 10);
  int tid = threadIdx.x;
  float4 v = *(float4*)&p[tid * 4];
  __shared__ float red[256];
  float mx = fmaxf(fmaxf(v.x, v.y), fmaxf(v.z, v.w));
  red[tid] = mx;
  __syncthreads();
  for (int s = 128; s > 0; s >>= 1) {
    if (tid < s) red[tid] = fmaxf(red[tid], red[tid + s]);
    __syncthreads();
  }
  mx = red[0];
  __syncthreads();
  v.x = __expf(v.x - mx); v.y = __expf(v.y - mx);
  v.z = __expf(v.z - mx); v.w = __expf(v.w - mx);
  red[tid] = (v.x + v.y) + (v.z + v.w);
  __syncthreads();
  for (int s = 128; s > 0; s >>= 1) {
    if (tid < s) red[tid] += red[tid + s];
    __syncthreads();
  }
  float inv = 1.0f / red[0];
  v.x *= inv; v.y *= inv; v.z *= inv; v.w *= inv;
  *(float4*)&p[tid * 4] = v;
}

// ===================== 6) column sums (deterministic 2-phase) ===============
__global__ void k_colsum_part(const float* __restrict__ attn, float* __restrict__ part) {
  int bh = blockIdx.x, ny = blockIdx.y, m = threadIdx.x;  // 32 x 8, 1024 thr
  const float* p = attn + ((size_t)bh << 20) + ((size_t)(ny * 128) << 10) + m;
  float a0 = 0, a1 = 0, a2 = 0, a3 = 0;
  for (int n = 0; n < 128; n += 4) {
    a0 += p[(size_t)(n + 0) << 10];
    a1 += p[(size_t)(n + 1) << 10];
    a2 += p[(size_t)(n + 2) << 10];
    a3 += p[(size_t)(n + 3) << 10];
  }
  part[(bh * 8 + ny) * 1024 + m] = (a0 + a1) + (a2 + a3);
}
__global__ void k_colsum_red(const float* __restrict__ part, float* __restrict__ score) {
  int bh = blockIdx.x, m = threadIdx.x;
  float a = 0;
#pragma unroll
  for (int i = 0; i < 8; i++) a += part[(bh * 8 + i) * 1024 + m];
  score[bh * 1024 + m] = a;
}

// ===================== 7) top-256 by rank (matches lax.top_k order) =========
__global__ void k_topk(const float* __restrict__ score, int* __restrict__ topk) {
  int bh = blockIdx.x;
  __shared__ float s[1024];
  int tid = threadIdx.x;   // 1024
  s[tid] = score[bh * 1024 + tid];
  __syncthreads();
  float mine = s[tid];
  int rank = 0;
  for (int j = 0; j < 1024; j++) {
    float o = s[j];
    rank += (o > mine) || (o == mine && j < tid);
  }
  if (rank < 256) topk[bh * 256 + rank] = tid;
}

// ===================== 8) out = attn @ v (tf32 tensor core) =================
// mode 0: write [bh][m][64] row-major (fine). mode 1: image layout aout.
__global__ void __launch_bounds__(256) k_av_t(const float* __restrict__ attn,
    const float* __restrict__ v, float* __restrict__ out, int mode) {
  __shared__ uint32 As[16][132];
  __shared__ uint32 Bs[16][68];
  float c[2][4][4] = {};
  int tid = threadIdx.x, lane = tid & 31, wid = tid >> 5;
  int wm = (wid & 3) * 32, wn = (wid >> 2) * 32;
  int bh = blockIdx.z, m0 = blockIdx.y * 128;
  const float* A  = attn + ((size_t)bh << 20);
  const float* Bm = v    + ((size_t)bh << 16);
  int bkk = tid >> 4, bnn = (tid & 15) * 4;
  for (int k0 = 0; k0 < 1024; k0 += 16) {
    ldA_tf32(As, A, 1024, m0, k0, tid);
    {
      float4 x = *(const float4*)(Bm + (size_t)(k0 + bkk) * 64 + bnn);
      Bs[bkk][bnn + 0] = tf32cvt(x.x); Bs[bkk][bnn + 1] = tf32cvt(x.y);
      Bs[bkk][bnn + 2] = tf32cvt(x.z); Bs[bkk][bnn + 3] = tf32cvt(x.w);
    }
    __syncthreads();
    mma_tile_tf32_32(As, Bs, c, lane, wm, wn);
    __syncthreads();
  }
  int g = lane >> 2, t2 = (lane & 3) * 2;
  if (mode == 0) {
    float* dst0 = out + ((size_t)bh << 16);
#pragma unroll
    for (int mi = 0; mi < 2; mi++) {
      int m = m0 + wm + mi * 16 + g;
#pragma unroll
      for (int ni = 0; ni < 4; ni++) {
        int col = wn + ni * 8 + t2;
        *(float2*)&dst0[((size_t)m << 6) + col] =
            make_float2(c[mi][ni][0], c[mi][ni][1]);
        *(float2*)&dst0[((size_t)(m + 8) << 6) + col] =
            make_float2(c[mi][ni][2], c[mi][ni][3]);
      }
    }
  } else {
    int b = bh >> 2, h = bh & 3;
#pragma unroll
    for (int mi = 0; mi < 2; mi++) {
      int m = m0 + wm + mi * 16 + g;
#pragma unroll
      for (int ni = 0; ni < 4; ni++) {
        int d = wn + ni * 8 + t2;
        float* base0 = &out[(((b << 8) + (h << 6) + d) << 10)];
        float* base1 = base0 + (1 << 10);
        base0[m]     = c[mi][ni][0];
        base1[m]     = c[mi][ni][1];
        base0[m + 8] = c[mi][ni][2];
        base1[m + 8] = c[mi][ni][3];
      }
    }
  }
}

// ===================== 9) ConvTranspose 4x4 s2 p1 — tf32 tensor core ========
// M=256 co, N=8192 (b, 32x32 half-res), K=1024 (ci*4 + tap). BM=128, BN=128.
__global__ void __launch_bounds__(256) k_conv_up_t(const float* __restrict__ ain,
    const float* __restrict__ wre, const float* __restrict__ bias,
    float* __restrict__ out) {
  __shared__ uint32 As[16][132];
  __shared__ uint32 Bs[16][132];
  float c[4][4][4] = {};
  int tid = threadIdx.x, lane = tid & 31, wid = tid >> 5;
  int wm = (wid & 1) * 64, wn = (wid >> 1) * 32;
  int m0 = blockIdx.y * 128, n0 = blockIdx.x * 128;
  int pc = blockIdx.z;
  int py = pc >> 1, px = pc & 1;
  const float* A = wre + (size_t)pc * 262144;
  int lkk = tid >> 4, lnn = (tid & 15) * 8;
  int dy0 = (py + 1) >> 1, dx0 = (px + 1) >> 1;
  int bimg = n0 >> 10, rem0 = (n0 & 1023) + lnn;
  const float* ab = ain + ((size_t)bimg << 18);
  for (int k0 = 0; k0 < 1024; k0 += 16) {
    ldA_tf32(As, A, 1024, m0, k0, tid);
    {
      int k = k0 + lkk;
      int ci = k >> 2, t = k & 3;
      int dy = dy0 - (t >> 1), dx = dx0 - (t & 1);
      const float* ac = ab + ((size_t)ci << 10);
#pragma unroll
      for (int j = 0; j < 8; j++) {
        int rem = rem0 + j;
        int iy = (rem >> 5) + dy, ix = (rem & 31) + dx;
        float vv = 0.f;
        if ((unsigned)iy < 32u && (unsigned)ix < 32u) vv = ac[(iy << 5) + ix];
        Bs[lkk][lnn + j] = tf32cvt(vv);
      }
    }
    __syncthreads();
    mma_tile_tf32(As, Bs, c, lane, wm, wn);
    __syncthreads();
  }
  int g = lane >> 2, t2 = (lane & 3) * 2;
#pragma unroll
  for (int mi = 0; mi < 4; mi++) {
    int m = m0 + wm + mi * 16 + g;
    float bi0 = bias[m], bi1 = bias[m + 8];
    float* base0 = &out[(((bimg << 8) + m) << 12)];
    float* base1 = base0 + (8 << 12);
#pragma unroll
    for (int ni = 0; ni < 4; ni++) {
      int ln = wn + ni * 8 + t2;
      int rem = (n0 & 1023) + ln;
      int oy2 = rem >> 5, ox2 = rem & 31;
      int off = ((2 * oy2 + py) << 6) + 2 * ox2 + px;
      base0[off]     = c[mi][ni][0] + bi0;
      base0[off + 2] = c[mi][ni][1] + bi0;
      base1[off]     = c[mi][ni][2] + bi1;
      base1[off + 2] = c[mi][ni][3] + bi1;
    }
  }
}

// ===================== 10) gather fine tokens ===============================
__global__ void k_gather(const float* __restrict__ coarse, const int* __restrict__ topk,
                         float* __restrict__ tok) {
  int bh = blockIdx.x, chunk = blockIdx.y;   // 32 x 16
  int tid = threadIdx.x;
  int d = tid & 63;
  int b = bh >> 2, h = bh & 3;
#pragma unroll
  for (int i = 0; i < 16; i++) {
    int j = chunk * 64 + (tid >> 6) + i * 4;  // token 0..1023
    int p = j >> 2, l = j & 3;
    int qq = topk[bh * 256 + p];
    int py = ((qq >> 5) << 1) + (l >> 1);
    int px = ((qq & 31) << 1) + (l & 1);
    tok[((size_t)bh << 16) + ((size_t)j << 6) + d] =
        coarse[(((b << 8) + (h << 6) + d) << 12) + (py << 6) + px];
  }
}

// ===================== 11) scatter-add fine outputs into coarse =============
__global__ void k_scatter(const float* __restrict__ outf, const int* __restrict__ topk,
                          float* __restrict__ coarse) {
  int bh = blockIdx.x, chunk = blockIdx.y;
  int tid = threadIdx.x;
  int d = tid & 63;
  int b = bh >> 2, h = bh & 3;
#pragma unroll
  for (int i = 0; i < 16; i++) {
    int j = chunk * 64 + (tid >> 6) + i * 4;
    int p = j >> 2, l = j & 3;
    int qq = topk[bh * 256 + p];
    int py = ((qq >> 5) << 1) + (l >> 1);
    int px = ((qq & 31) << 1) + (l & 1);
    coarse[(((b << 8) + (h << 6) + d) << 12) + (py << 6) + px] +=
        outf[((size_t)bh << 16) + ((size_t)j << 6) + d];
  }
}

// ===================== 12) depthwise 3x3 + BN1 + ReLU6 ======================
__global__ void k_dw(const float* __restrict__ y, const float* __restrict__ w,
    const float* __restrict__ g, const float* __restrict__ bb,
    const float* __restrict__ mm, const float* __restrict__ vv,
    float* __restrict__ out) {
  int idx = blockIdx.x * 256 + threadIdx.x;   // 8*256*4096
  int x = idx & 63, yy = (idx >> 6) & 63, c = (idx >> 12) & 255, b = idx >> 20;
  const float* base = y + ((size_t)((b << 8) + c) << 12);
  float acc = 0.f;
#pragma unroll
  for (int ky = 0; ky < 3; ky++) {
    int iy = yy + ky - 1;
    if ((unsigned)iy >= 64u) continue;
#pragma unroll
    for (int kx = 0; kx < 3; kx++) {
      int ix = x + kx - 1;
      if ((unsigned)ix >= 64u) continue;
      acc += w[c * 9 + ky * 3 + kx] * base[(iy << 6) + ix];
    }
  }
  float inv = g[c] * rsqrtf(vv[c] + 1e-5f);
  float val = acc * inv + (bb[c] - mm[c] * inv);
  out[idx] = fminf(fmaxf(val, 0.f), 6.f);
}

// ===================== 13) pointwise 1x1 + BN2 + ReLU6 — tf32 tensor core ===
// M=256 co, N=32768 (b, 64x64), K=256. BM=128, BN=128.
__global__ void __launch_bounds__(256) k_pw_t(const float* __restrict__ y1,
    const float* __restrict__ w, const float* __restrict__ bn_g,
    const float* __restrict__ bn_b, const float* __restrict__ bn_m,
    const float* __restrict__ bn_v, float* __restrict__ out) {
  __shared__ uint32 As[16][132];
  __shared__ uint32 Bs[16][132];
  float c[4][4][4] = {};
  int tid = threadIdx.x, lane = tid & 31, wid = tid >> 5;
  int wm = (wid & 1) * 64, wn = (wid >> 1) * 32;
  int m0 = blockIdx.y * 128, n0 = blockIdx.x * 128;
  int lkk = tid >> 4, lnn = (tid & 15) * 8;
  int bB = n0 >> 12, remB = (n0 & 4095) + lnn;
  const float* yb = y1 + ((size_t)bB << 20);
  for (int k0 = 0; k0 < 256; k0 += 16) {
    ldA_tf32(As, w, 256, m0, k0, tid);
    {
      const float* src = yb + ((size_t)(k0 + lkk) << 12) + remB;
      float4 x0 = *(const float4*)(src);
      float4 x1 = *(const float4*)(src + 4);
      Bs[lkk][lnn + 0] = tf32cvt(x0.x); Bs[lkk][lnn + 1] = tf32cvt(x0.y);
      Bs[lkk][lnn + 2] = tf32cvt(x0.z); Bs[lkk][lnn + 3] = tf32cvt(x0.w);
      Bs[lkk][lnn + 4] = tf32cvt(x1.x); Bs[lkk][lnn + 5] = tf32cvt(x1.y);
      Bs[lkk][lnn + 6] = tf32cvt(x1.z); Bs[lkk][lnn + 7] = tf32cvt(x1.w);
    }
    __syncthreads();
    mma_tile_tf32(As, Bs, c, lane, wm, wn);
    __syncthreads();
  }
  int g = lane >> 2, t2 = (lane & 3) * 2;
#pragma unroll
  for (int mi = 0; mi < 4; mi++) {
    int m = m0 + wm + mi * 16 + g;
    float inv0 = bn_g[m] * rsqrtf(bn_v[m] + 1e-5f);
    float add0 = bn_b[m] - bn_m[m] * inv0;
    float inv1 = bn_g[m + 8] * rsqrtf(bn_v[m + 8] + 1e-5f);
    float add1 = bn_b[m + 8] - bn_m[m + 8] * inv1;
    float* base0 = &out[(((size_t)(bB << 8) + m) << 12)];
    float* base1 = base0 + (8 << 12);
#pragma unroll
    for (int ni = 0; ni < 4; ni++) {
      int rem = (n0 & 4095) + wn + ni * 8 + t2;
      float2 o0, o1;
      o0.x = fminf(fmaxf(c[mi][ni][0] * inv0 + add0, 0.f), 6.f);
      o0.y = fminf(fmaxf(c[mi][ni][1] * inv0 + add0, 0.f), 6.f);
      o1.x = fminf(fmaxf(c[mi][ni][2] * inv1 + add1, 0.f), 6.f);
      o1.y = fminf(fmaxf(c[mi][ni][3] * inv1 + add1, 0.f), 6.f);
      *(float2*)&base0[rem] = o0;
      *(float2*)&base1[rem] = o1;
    }
  }
}

// ===================== host launcher ========================================
static float* symf(const void* s) {
  void* p = nullptr;
  cudaGetSymbolAddress(&p, s);
  return (float*)p;
}

extern "C" void kernel_launch(void* const* d_in, const int* in_sizes, int n_in,
                              void* d_out, int out_size) {
  const float* x      = (const float*)d_in[0];
  const float* down_w = (const float*)d_in[1];
  const float* down_b = (const float*)d_in[2];
  const float* up_w   = (const float*)d_in[3];
  const float* up_b   = (const float*)d_in[4];
  const float* wqkv_c = (const float*)d_in[5];
  const float* bqkv_c = (const float*)d_in[6];
  const float* wqkv_f = (const float*)d_in[7];
  const float* bqkv_f = (const float*)d_in[8];
  const float* dw_w   = (const float*)d_in[9];
  const float* bn1_g  = (const float*)d_in[10];
  const float* bn1_b  = (const float*)d_in[11];
  const float* bn1_m  = (const float*)d_in[12];
  const float* bn1_v  = (const float*)d_in[13];
  const float* pw_w   = (const float*)d_in[14];
  const float* bn2_g  = (const float*)d_in[15];
  const float* bn2_b  = (const float*)d_in[16];
  const float* bn2_m  = (const float*)d_in[17];
  const float* bn2_v  = (const float*)d_in[18];
  float* out = (float*)d_out;

  float* xd     = symf(g_xd);
  float* tok    = symf(g_tok);
  float* q      = symf(g_q);
  float* kk     = symf(g_kk);
  float* v      = symf(g_v);
  float* attn   = symf(g_attn);
  float* part   = symf(g_part);
  float* score  = symf(g_score);
  int*   topk   = (int*)symf(g_topk);
  float* aout   = symf(g_aout);
  float* coarse = symf(g_coarse);
  float* outf   = symf(g_outf);
  float* y1     = symf(g_y1);
  float* upw    = symf(g_upw);

  // ---- coarse branch ----
  k_repack_upw<<<4096, 256>>>(up_w, upw);
  k_conv_down<<<dim3(128, 2), 256>>>(x, down_w, down_b, xd);
  k_tokc<<<dim3(32, 16), 256>>>(xd, tok);
  k_qkv<<<dim3(3, 8, 32), 256>>>(tok, wqkv_c, bqkv_c, q, kk, v);
  k_qkT<<<dim3(16, 8, 32), 256>>>(q, kk, attn);
  k_softmax<<<dim3(1024, 32), 256>>>(attn);
  k_colsum_part<<<dim3(32, 8), 1024>>>(attn, part);
  k_colsum_red<<<32, 1024>>>(part, score);
  k_topk<<<32, 1024>>>(score, topk);
  k_av_t<<<dim3(1, 8, 32), 256>>>(attn, v, aout, 1);
  k_conv_up_t<<<dim3(64, 2, 4), 256>>>(aout, upw, up_b, coarse);

  // ---- fine branch ----
  k_gather<<<dim3(32, 16), 256>>>(coarse, topk, tok);
  k_qkv<<<dim3(3, 8, 32), 256>>>(tok, wqkv_f, bqkv_f, q, kk, v);
  k_qkT_t<<<dim3(8, 8, 32), 256>>>(q, kk, attn);
  k_softmax<<<dim3(1024, 32), 256>>>(attn);
  k_av_t<<<dim3(1, 8, 32), 256>>>(attn, v, outf, 0);
  k_scatter<<<dim3(32, 16), 256>>>(outf, topk, coarse);

  // ---- DWConv block ----
  k_dw<<<32768, 256>>>(coarse, dw_w, bn1_g, bn1_b, bn1_m, bn1_v, y1);
  k_pw_t<<<dim3(256, 2), 256>>>(y1, pw_w, bn2_g, bn2_b, bn2_m, bn2_v, out);
}